// round 1
// baseline (speedup 1.0000x reference)
#include <cuda_runtime.h>
#include <math.h>
#include <stdint.h>

#define BATCH 1024
#define DIN 103
#define L1W 64
#define L2W 32
#define NE 8
#define GHW 64
#define HID 256
#define DOUT 51

// ---------------- scratch (device globals; no allocation allowed) ----------------
__device__ float g_xs[BATCH * DIN];
__device__ float g_enc1[BATCH * L1W];
__device__ float g_lat[BATCH * L2W];
__device__ float g_bc[BATCH * NE];
__device__ float g_h1[BATCH * HID];
__device__ float g_h2[BATCH * HID];
__device__ float g_part[NE * BATCH * HID];   // per-expert partials (8 MB)

// ---------------- scale last 3 features by 100 ----------------
__global__ void scale_kernel(const float* __restrict__ x) {
    int i = blockIdx.x * 256 + threadIdx.x;
    if (i < BATCH * DIN) {
        float v = x[i];
        if ((i % DIN) >= 100) v *= 100.0f;
        g_xs[i] = v;
    }
}

// ---------------- encoder: Linear + batch BN + ReLU, one block per feature ----------------
template <int IN>
__global__ __launch_bounds__(256)
void enc_bn_relu_kernel(const float* __restrict__ in, int OUT,
                        const float* __restrict__ w, const float* __restrict__ b,
                        const float* __restrict__ gamma, const float* __restrict__ beta,
                        float* __restrict__ out) {
    const int f = blockIdx.x;
    __shared__ float wf[IN];
    __shared__ float red[18];
    const int t = threadIdx.x;
    if (t < IN) wf[t] = w[f * IN + t];
    __syncthreads();

    const float bf = b[f];
    float z[4];
    float s = 0.f, s2 = 0.f;
#pragma unroll
    for (int r = 0; r < 4; r++) {
        int row = t + 256 * r;
        const float* xr = in + (size_t)row * IN;
        float acc = 0.f;
#pragma unroll 4
        for (int i = 0; i < IN; i++) acc = fmaf(xr[i], wf[i], acc);
        acc += bf;
        z[r] = acc;
        s += acc;
        s2 = fmaf(acc, acc, s2);
    }
    // block reduction of sum and sumsq
#pragma unroll
    for (int o = 16; o > 0; o >>= 1) {
        s  += __shfl_xor_sync(0xFFFFFFFFu, s,  o);
        s2 += __shfl_xor_sync(0xFFFFFFFFu, s2, o);
    }
    int warp = t >> 5, lane = t & 31;
    if (lane == 0) { red[warp] = s; red[8 + warp] = s2; }
    __syncthreads();
    if (t == 0) {
        float S = 0.f, S2 = 0.f;
        for (int i = 0; i < 8; i++) { S += red[i]; S2 += red[8 + i]; }
        float mean = S * (1.0f / BATCH);
        float var  = S2 * (1.0f / BATCH) - mean * mean;
        float sc = gamma[f] * rsqrtf(var + 1e-5f);
        red[16] = sc;
        red[17] = beta[f] - mean * sc;
    }
    __syncthreads();
    float sc = red[16], sh = red[17];
#pragma unroll
    for (int r = 0; r < 4; r++) {
        int row = t + 256 * r;
        out[(size_t)row * OUT + f] = fmaxf(fmaf(z[r], sc, sh), 0.f);
    }
}

// ---------------- gating MLP fully fused: latent -> ELU -> ELU -> softmax(8) ----------------
__global__ __launch_bounds__(512)
void gating_kernel(const float* __restrict__ lat,
                   const float* __restrict__ gw1, const float* __restrict__ gb1,
                   const float* __restrict__ gw2, const float* __restrict__ gb2,
                   const float* __restrict__ gw3, const float* __restrict__ gb3) {
    __shared__ float s_gw1[GHW * L2W];
    __shared__ float s_gw2[GHW * GHW];
    __shared__ float s_gw3[NE * GHW];
    __shared__ float s_gb1[GHW], s_gb2[GHW], s_gb3[NE];
    __shared__ float s_lat[8][L2W];
    __shared__ float s_g1[8][GHW];
    __shared__ float s_g2[8][GHW];
    __shared__ float s_lg[8][NE];

    const int tx = threadIdx.x;   // 64
    const int ty = threadIdx.y;   // 8
    const int tid = ty * 64 + tx; // 512
    const int b0 = blockIdx.x * 8;

    for (int i = tid; i < GHW * L2W; i += 512) s_gw1[i] = gw1[i];
    for (int i = tid; i < GHW * GHW; i += 512) s_gw2[i] = gw2[i];
    for (int i = tid; i < NE * GHW; i += 512) s_gw3[i] = gw3[i];
    if (tid < GHW) { s_gb1[tid] = gb1[tid]; s_gb2[tid] = gb2[tid]; }
    if (tid < NE)  s_gb3[tid] = gb3[tid];
    if (tx < L2W)  s_lat[ty][tx] = lat[(size_t)(b0 + ty) * L2W + tx];
    __syncthreads();

    float acc = s_gb1[tx];
#pragma unroll
    for (int k = 0; k < L2W; k++) acc = fmaf(s_lat[ty][k], s_gw1[tx * L2W + k], acc);
    s_g1[ty][tx] = (acc > 0.f) ? acc : expm1f(acc);
    __syncthreads();

    acc = s_gb2[tx];
#pragma unroll
    for (int k = 0; k < GHW; k++) acc = fmaf(s_g1[ty][k], s_gw2[tx * GHW + k], acc);
    s_g2[ty][tx] = (acc > 0.f) ? acc : expm1f(acc);
    __syncthreads();

    if (tx < NE) {
        acc = s_gb3[tx];
#pragma unroll
        for (int k = 0; k < GHW; k++) acc = fmaf(s_g2[ty][k], s_gw3[tx * GHW + k], acc);
        s_lg[ty][tx] = acc;
    }
    __syncthreads();

    if (tx == 0) {
        float m = s_lg[ty][0];
#pragma unroll
        for (int e = 1; e < NE; e++) m = fmaxf(m, s_lg[ty][e]);
        float ex[NE];
        float ssum = 0.f;
#pragma unroll
        for (int e = 0; e < NE; e++) { ex[e] = expf(s_lg[ty][e] - m); ssum += ex[e]; }
        float inv = 1.0f / ssum;
#pragma unroll
        for (int e = 0; e < NE; e++) g_bc[(size_t)(b0 + ty) * NE + e] = ex[e] * inv;
    }
}

// ---------------- generator layer: per-expert GEMM tile, bc-weighted partial ----------------
// out_partial[e][b][n] = bc[b][e] * (sum_k A[b][k] * W[e][k][n] + bias[e][n])
// Tile: BM=64 x BN=32, 128 threads, TM=4 x TN=4 per thread.
template <int IN>
__global__ __launch_bounds__(128)
void gen_expert_kernel(const float* __restrict__ A,
                       const float* __restrict__ W,
                       const float* __restrict__ bias,
                       float* __restrict__ part,
                       int OUT) {
    constexpr int BM = 64, BN = 32, BK = 16;
    constexpr int KT = (IN + BK - 1) / BK;
    __shared__ float As[BK][BM];
    __shared__ float Ws[BK][BN];

    const int e  = blockIdx.z;
    const int m0 = blockIdx.y * BM;
    const int n0 = blockIdx.x * BN;
    const int tid = threadIdx.x;        // 128
    const int tx = tid & 7;             // 8 col-groups of 4
    const int ty = tid >> 3;            // 16 row-groups of 4

    // A tile load map: 64x16 = 1024 elems, 8 per thread
    const int a_m  = tid >> 1;          // 0..63
    const int a_k0 = (tid & 1) * 8;     // 0 or 8
    // W tile load map: 16x32 = 512 elems, 4 per thread
    const int w_k = tid >> 3;           // 0..15
    const int w_n = (tid & 7) * 4;      // 0..28

    const float* Wbase = W + (size_t)e * IN * OUT;

    float acc[4][4] = {};

    for (int kt = 0; kt < KT; kt++) {
        const int k0 = kt * BK;
        __syncthreads();
#pragma unroll
        for (int j = 0; j < 8; j++) {
            int k = a_k0 + j;
            int gk = k0 + k;
            As[k][a_m] = (gk < IN) ? A[(size_t)(m0 + a_m) * IN + gk] : 0.f;
        }
        {
            int gk = k0 + w_k;
            bool kok = (gk < IN);
            const float* wp = Wbase + (size_t)gk * OUT + n0 + w_n;
#pragma unroll
            for (int j = 0; j < 4; j++) {
                int n = n0 + w_n + j;
                Ws[w_k][w_n + j] = (kok && n < OUT) ? wp[j] : 0.f;
            }
        }
        __syncthreads();
#pragma unroll
        for (int k = 0; k < BK; k++) {
            float a[4], w[4];
#pragma unroll
            for (int i = 0; i < 4; i++) a[i] = As[k][ty * 4 + i];
#pragma unroll
            for (int j = 0; j < 4; j++) w[j] = Ws[k][tx * 4 + j];
#pragma unroll
            for (int i = 0; i < 4; i++)
#pragma unroll
                for (int j = 0; j < 4; j++)
                    acc[i][j] = fmaf(a[i], w[j], acc[i][j]);
        }
    }

#pragma unroll
    for (int i = 0; i < 4; i++) {
        const int row = m0 + ty * 4 + i;
        const float bcv = g_bc[(size_t)row * NE + e];
#pragma unroll
        for (int j = 0; j < 4; j++) {
            const int n = n0 + tx * 4 + j;
            if (n < OUT) {
                float bv = bias[(size_t)e * OUT + n];
                part[((size_t)e * BATCH + row) * OUT + n] = bcv * (acc[i][j] + bv);
            }
        }
    }
}

// ---------------- combine experts (+ optional ELU) ----------------
template <bool ACT>
__global__ void combine_kernel(const float* __restrict__ part, float* __restrict__ out, int OUT) {
    const int total = BATCH * OUT;
    int i = blockIdx.x * 256 + threadIdx.x;
    if (i < total) {
        float s = 0.f;
#pragma unroll
        for (int e = 0; e < NE; e++) s += part[(size_t)e * total + i];
        if (ACT) s = (s > 0.f) ? s : expm1f(s);
        out[i] = s;
    }
}

// ---------------- launch ----------------
extern "C" void kernel_launch(void* const* d_in, const int* in_sizes, int n_in,
                              void* d_out, int out_size) {
    const float* x      = (const float*)d_in[0];
    const float* w1     = (const float*)d_in[1];
    const float* b1     = (const float*)d_in[2];
    const float* gamma1 = (const float*)d_in[3];
    const float* beta1  = (const float*)d_in[4];
    const float* w2     = (const float*)d_in[5];
    const float* b2     = (const float*)d_in[6];
    const float* gamma2 = (const float*)d_in[7];
    const float* beta2  = (const float*)d_in[8];
    const float* gw1    = (const float*)d_in[9];
    const float* gb1    = (const float*)d_in[10];
    const float* gw2    = (const float*)d_in[11];
    const float* gb2    = (const float*)d_in[12];
    const float* gw3    = (const float*)d_in[13];
    const float* gb3    = (const float*)d_in[14];
    const float* ew1    = (const float*)d_in[15];
    const float* eb1    = (const float*)d_in[16];
    const float* ew2    = (const float*)d_in[17];
    const float* eb2    = (const float*)d_in[18];
    const float* ew3    = (const float*)d_in[19];
    const float* eb3    = (const float*)d_in[20];

    float *p_xs, *p_enc1, *p_lat, *p_h1, *p_h2, *p_part;
    cudaGetSymbolAddress((void**)&p_xs,   g_xs);
    cudaGetSymbolAddress((void**)&p_enc1, g_enc1);
    cudaGetSymbolAddress((void**)&p_lat,  g_lat);
    cudaGetSymbolAddress((void**)&p_h1,   g_h1);
    cudaGetSymbolAddress((void**)&p_h2,   g_h2);
    cudaGetSymbolAddress((void**)&p_part, g_part);

    scale_kernel<<<(BATCH * DIN + 255) / 256, 256>>>(x);

    enc_bn_relu_kernel<DIN><<<L1W, 256>>>(p_xs, L1W, w1, b1, gamma1, beta1, p_enc1);
    enc_bn_relu_kernel<L1W><<<L2W, 256>>>(p_enc1, L2W, w2, b2, gamma2, beta2, p_lat);

    gating_kernel<<<BATCH / 8, dim3(64, 8)>>>(p_lat, gw1, gb1, gw2, gb2, gw3, gb3);

    // generator layer 1: xs[1024,103] x ew1[8,103,256]
    gen_expert_kernel<DIN><<<dim3(HID / 32, BATCH / 64, NE), 128>>>(p_xs, ew1, eb1, p_part, HID);
    combine_kernel<true><<<(BATCH * HID + 255) / 256, 256>>>(p_part, p_h1, HID);

    // generator layer 2: h1[1024,256] x ew2[8,256,256]
    gen_expert_kernel<HID><<<dim3(HID / 32, BATCH / 64, NE), 128>>>(p_h1, ew2, eb2, p_part, HID);
    combine_kernel<true><<<(BATCH * HID + 255) / 256, 256>>>(p_part, p_h2, HID);

    // generator layer 3: h2[1024,256] x ew3[8,256,51]
    gen_expert_kernel<HID><<<dim3((DOUT + 31) / 32, BATCH / 64, NE), 128>>>(p_h2, ew3, eb3, p_part, DOUT);
    combine_kernel<false><<<(BATCH * DOUT + 255) / 256, 256>>>(p_part, (float*)d_out, DOUT);
}

// round 4
// speedup vs baseline: 1.1842x; 1.1842x over previous
#include <cuda_runtime.h>
#include <math.h>
#include <stdint.h>

#define BATCH 1024
#define DIN 103
#define XPAD 128
#define L1W 64
#define L2W 32
#define NE 8
#define GHW 64
#define HID 256
#define DOUT 51
#define DOPAD 64

// ---------------- scratch ----------------
__device__ float g_xs[BATCH * XPAD];          // padded input (zeros beyond 103)
__device__ float g_enc1[BATCH * L1W];
__device__ float g_lat[BATCH * L2W];
__device__ float g_bc[BATCH * NE];
__device__ float g_h1[BATCH * HID];
__device__ float g_h2[BATCH * HID];
__device__ float g_w3p[NE * HID * DOPAD];     // ew3 padded 51->64
__device__ float g_b3p[NE * DOPAD];
__device__ float g_part[NE * BATCH * HID];    // per-expert partials (8 MB)

// ---------------- prep: scale+pad xs, pad ew3/eb3 ----------------
__global__ void prep_kernel(const float* __restrict__ x,
                            const float* __restrict__ ew3,
                            const float* __restrict__ eb3) {
    int i = blockIdx.x * 256 + threadIdx.x;
    const int N1 = BATCH * XPAD;            // 131072
    const int N2 = NE * HID * DOPAD;        // 131072
    if (i < N1) {
        int b = i >> 7, c = i & 127;
        float v = 0.f;
        if (c < DIN) {
            v = x[b * DIN + c];
            if (c >= 100) v *= 100.0f;
        }
        g_xs[i] = v;
    } else if (i < N1 + N2) {
        int j = i - N1;
        int c = j & 63;
        int er = j >> 6;                    // e*HID + r
        g_w3p[j] = (c < DOUT) ? ew3[er * DOUT + c] : 0.f;
    } else if (i < N1 + N2 + NE * DOPAD) {
        int j = i - N1 - N2;
        int e = j >> 6, c = j & 63;
        g_b3p[j] = (c < DOUT) ? eb3[e * DOUT + c] : 0.f;
    }
}

// ---------------- encoder: Linear + batch BN + ReLU, one block per feature ----------------
template <int IN, int SIN, int SOUT>
__global__ __launch_bounds__(256)
void enc_bn_relu_kernel(const float* __restrict__ in,
                        const float* __restrict__ w, const float* __restrict__ b,
                        const float* __restrict__ gamma, const float* __restrict__ beta,
                        float* __restrict__ out) {
    const int f = blockIdx.x;
    __shared__ float wf[IN];
    __shared__ float red[18];
    const int t = threadIdx.x;
    if (t < IN) wf[t] = w[f * IN + t];
    __syncthreads();

    const float bf = b[f];
    float z[4];
    float s = 0.f, s2 = 0.f;
#pragma unroll
    for (int r = 0; r < 4; r++) {
        int row = t + 256 * r;
        const float* xr = in + (size_t)row * SIN;
        float acc = 0.f;
#pragma unroll 4
        for (int i = 0; i < IN; i++) acc = fmaf(xr[i], wf[i], acc);
        acc += bf;
        z[r] = acc;
        s += acc;
        s2 = fmaf(acc, acc, s2);
    }
#pragma unroll
    for (int o = 16; o > 0; o >>= 1) {
        s  += __shfl_xor_sync(0xFFFFFFFFu, s,  o);
        s2 += __shfl_xor_sync(0xFFFFFFFFu, s2, o);
    }
    int warp = t >> 5, lane = t & 31;
    if (lane == 0) { red[warp] = s; red[8 + warp] = s2; }
    __syncthreads();
    if (t == 0) {
        float S = 0.f, S2 = 0.f;
        for (int i = 0; i < 8; i++) { S += red[i]; S2 += red[8 + i]; }
        float mean = S * (1.0f / BATCH);
        float var  = S2 * (1.0f / BATCH) - mean * mean;
        float sc = gamma[f] * rsqrtf(var + 1e-5f);
        red[16] = sc;
        red[17] = beta[f] - mean * sc;
    }
    __syncthreads();
    float sc = red[16], sh = red[17];
#pragma unroll
    for (int r = 0; r < 4; r++) {
        int row = t + 256 * r;
        out[(size_t)row * SOUT + f] = fmaxf(fmaf(z[r], sc, sh), 0.f);
    }
}

// ---------------- gating MLP: 16 rows/block, 256 threads, conflict-free smem ----------------
__global__ __launch_bounds__(256)
void gating_kernel(const float* __restrict__ lat,
                   const float* __restrict__ gw1, const float* __restrict__ gb1,
                   const float* __restrict__ gw2, const float* __restrict__ gb2,
                   const float* __restrict__ gw3, const float* __restrict__ gb3) {
    __shared__ float s_gw1[L2W * 65];      // [k][o], stride 65
    __shared__ float s_gw2[GHW * 65];      // [k][o], stride 65
    __shared__ float s_gw3[GHW * NE];      // [k][e]
    __shared__ float s_gb1[GHW], s_gb2[GHW], s_gb3[NE];
    __shared__ float s_lat[16][L2W];
    __shared__ float s_a1[16][GHW];
    __shared__ float s_a2[16][GHW];
    __shared__ float s_lg[16][NE];

    const int tid = threadIdx.x;
    const int ox = tid & 63;               // output index
    const int rg = tid >> 6;               // row group 0..3
    const int b0 = blockIdx.x * 16;

    // transposed weight loads (coalesced gmem, padded smem stride -> conflict-free)
    for (int i = tid; i < GHW * L2W; i += 256) {
        int o = i >> 5, k = i & 31;        // gw1[o][k]
        s_gw1[k * 65 + o] = gw1[i];
    }
    for (int i = tid; i < GHW * GHW; i += 256) {
        int o = i >> 6, k = i & 63;
        s_gw2[k * 65 + o] = gw2[i];
    }
    for (int i = tid; i < NE * GHW; i += 256) {
        int e = i >> 6, k = i & 63;
        s_gw3[k * NE + e] = gw3[i];
    }
    if (tid < GHW) { s_gb1[tid] = gb1[tid]; s_gb2[tid] = gb2[tid]; }
    if (tid < NE)  s_gb3[tid] = gb3[tid];
    for (int i = tid; i < 16 * L2W; i += 256) {
        int r = i >> 5, k = i & 31;
        s_lat[r][k] = lat[(size_t)(b0 + r) * L2W + k];
    }
    __syncthreads();

    // layer 1: 32 -> 64, ELU; 4 rows per thread for ILP
    {
        float acc[4];
#pragma unroll
        for (int j = 0; j < 4; j++) acc[j] = s_gb1[ox];
#pragma unroll
        for (int k = 0; k < L2W; k++) {
            float w = s_gw1[k * 65 + ox];
#pragma unroll
            for (int j = 0; j < 4; j++) acc[j] = fmaf(s_lat[rg * 4 + j][k], w, acc[j]);
        }
#pragma unroll
        for (int j = 0; j < 4; j++)
            s_a1[rg * 4 + j][ox] = (acc[j] > 0.f) ? acc[j] : expm1f(acc[j]);
    }
    __syncthreads();

    // layer 2: 64 -> 64, ELU
    {
        float acc[4];
#pragma unroll
        for (int j = 0; j < 4; j++) acc[j] = s_gb2[ox];
#pragma unroll
        for (int k = 0; k < GHW; k++) {
            float w = s_gw2[k * 65 + ox];
#pragma unroll
            for (int j = 0; j < 4; j++) acc[j] = fmaf(s_a1[rg * 4 + j][k], w, acc[j]);
        }
#pragma unroll
        for (int j = 0; j < 4; j++)
            s_a2[rg * 4 + j][ox] = (acc[j] > 0.f) ? acc[j] : expm1f(acc[j]);
    }
    __syncthreads();

    // layer 3: 64 -> 8 logits; 128 threads (e = tid%8, row = tid/8)
    if (tid < 128) {
        int e = tid & 7, r = tid >> 3;
        float acc = s_gb3[e];
#pragma unroll
        for (int k = 0; k < GHW; k++) acc = fmaf(s_a2[r][k], s_gw3[k * NE + e], acc);
        s_lg[r][e] = acc;
    }
    __syncthreads();

    // softmax per row
    if (tid < 16) {
        float m = s_lg[tid][0];
#pragma unroll
        for (int e = 1; e < NE; e++) m = fmaxf(m, s_lg[tid][e]);
        float ex[NE];
        float ssum = 0.f;
#pragma unroll
        for (int e = 0; e < NE; e++) { ex[e] = expf(s_lg[tid][e] - m); ssum += ex[e]; }
        float inv = 1.0f / ssum;
#pragma unroll
        for (int e = 0; e < NE; e++) g_bc[(size_t)(b0 + tid) * NE + e] = ex[e] * inv;
    }
}

// ---------------- generator layer GEMM: per-expert, BM=64 BN=64 BK=32, 256 thr, 4x4 ----------------
// part[e][b][n] = sum_k A[b][k] * W[e][k][n] + bias[e][n]
template <int KSIZE, int ASTRIDE, int OUTN, int INREAL>
__global__ __launch_bounds__(256)
void gen_expert_kernel(const float* __restrict__ A,
                       const float* __restrict__ W,
                       const float* __restrict__ bias,
                       float* __restrict__ part) {
    constexpr int BM = 64, BN = 64, BK = 32;
    constexpr int KT = KSIZE / BK;
    __shared__ float As[BK][BM + 4];
    __shared__ float Ws[BK][BN];
    __shared__ float sbias[BN];

    const int e  = blockIdx.z;
    const int m0 = blockIdx.y * BM;
    const int n0 = blockIdx.x * BN;
    const int tid = threadIdx.x;
    const int tx = tid & 15;
    const int ty = tid >> 4;

    // A load map: thread -> row am, 2 float4 at cols ak, ak+16
    const int am = tid >> 2;
    const int ak = (tid & 3) * 4;
    // W load map: thread -> row wk, 2 float4 at cols wc, wc+4
    const int wk = tid >> 3;
    const int wc = (tid & 7) * 8;

    const float* Wbase = W + (size_t)e * INREAL * OUTN;
    if (tid < BN) sbias[tid] = bias[(size_t)e * OUTN + n0 + tid];

    float acc[4][4] = {};

    for (int kt = 0; kt < KT; kt++) {
        const int k0 = kt * BK;
        __syncthreads();
        // A tile (transpose on store)
        {
            const float* ap = A + (size_t)(m0 + am) * ASTRIDE + k0;
            float4 v0 = *(const float4*)(ap + ak);
            float4 v1 = *(const float4*)(ap + ak + 16);
            As[ak + 0][am] = v0.x; As[ak + 1][am] = v0.y;
            As[ak + 2][am] = v0.z; As[ak + 3][am] = v0.w;
            As[ak + 16][am] = v1.x; As[ak + 17][am] = v1.y;
            As[ak + 18][am] = v1.z; As[ak + 19][am] = v1.w;
        }
        // W tile (clamp k index when K is padded past INREAL; A pad is zero)
        {
            int gk = k0 + wk;
            if (KSIZE != INREAL) gk = (gk < INREAL) ? gk : (INREAL - 1);
            const float* wp = Wbase + (size_t)gk * OUTN + n0;
            *(float4*)&Ws[wk][wc]     = *(const float4*)(wp + wc);
            *(float4*)&Ws[wk][wc + 4] = *(const float4*)(wp + wc + 4);
        }
        __syncthreads();
#pragma unroll
        for (int k = 0; k < BK; k++) {
            float4 a = *(const float4*)&As[k][ty * 4];
            float4 w = *(const float4*)&Ws[k][tx * 4];
            acc[0][0] = fmaf(a.x, w.x, acc[0][0]);
            acc[0][1] = fmaf(a.x, w.y, acc[0][1]);
            acc[0][2] = fmaf(a.x, w.z, acc[0][2]);
            acc[0][3] = fmaf(a.x, w.w, acc[0][3]);
            acc[1][0] = fmaf(a.y, w.x, acc[1][0]);
            acc[1][1] = fmaf(a.y, w.y, acc[1][1]);
            acc[1][2] = fmaf(a.y, w.z, acc[1][2]);
            acc[1][3] = fmaf(a.y, w.w, acc[1][3]);
            acc[2][0] = fmaf(a.z, w.x, acc[2][0]);
            acc[2][1] = fmaf(a.z, w.y, acc[2][1]);
            acc[2][2] = fmaf(a.z, w.z, acc[2][2]);
            acc[2][3] = fmaf(a.z, w.w, acc[2][3]);
            acc[3][0] = fmaf(a.w, w.x, acc[3][0]);
            acc[3][1] = fmaf(a.w, w.y, acc[3][1]);
            acc[3][2] = fmaf(a.w, w.z, acc[3][2]);
            acc[3][3] = fmaf(a.w, w.w, acc[3][3]);
        }
    }

#pragma unroll
    for (int i = 0; i < 4; i++) {
        const int row = m0 + ty * 4 + i;
        float* pp = part + ((size_t)e * BATCH + row) * OUTN + n0 + tx * 4;
        float4 o;
        o.x = acc[i][0] + sbias[tx * 4 + 0];
        o.y = acc[i][1] + sbias[tx * 4 + 1];
        o.z = acc[i][2] + sbias[tx * 4 + 2];
        o.w = acc[i][3] + sbias[tx * 4 + 3];
        *(float4*)pp = o;
    }
}

// ---------------- combine experts with bc weights (+ optional ELU), vectorized ----------------
template <bool ACT>
__global__ void combine_vec_kernel(const float* __restrict__ part, float* __restrict__ out) {
    // OUT = 256, float4 lanes
    const int i = blockIdx.x * 256 + threadIdx.x;       // 0 .. BATCH*64-1
    if (i >= BATCH * (HID / 4)) return;
    const int b = i >> 6;
    const float* bcp = g_bc + (size_t)b * NE;
    float4 s = make_float4(0.f, 0.f, 0.f, 0.f);
#pragma unroll
    for (int e = 0; e < NE; e++) {
        float c = bcp[e];
        float4 p = ((const float4*)part)[(size_t)e * BATCH * (HID / 4) + i];
        s.x = fmaf(c, p.x, s.x);
        s.y = fmaf(c, p.y, s.y);
        s.z = fmaf(c, p.z, s.z);
        s.w = fmaf(c, p.w, s.w);
    }
    if (ACT) {
        s.x = (s.x > 0.f) ? s.x : expm1f(s.x);
        s.y = (s.y > 0.f) ? s.y : expm1f(s.y);
        s.z = (s.z > 0.f) ? s.z : expm1f(s.z);
        s.w = (s.w > 0.f) ? s.w : expm1f(s.w);
    }
    ((float4*)out)[i] = s;
}

// final combine: padded stride 64 -> write 51
__global__ void combine_final_kernel(const float* __restrict__ part, float* __restrict__ out) {
    const int i = blockIdx.x * 256 + threadIdx.x;
    if (i >= BATCH * DOUT) return;
    const int b = i / DOUT;
    const int n = i - b * DOUT;
    const float* bcp = g_bc + (size_t)b * NE;
    float s = 0.f;
#pragma unroll
    for (int e = 0; e < NE; e++)
        s = fmaf(bcp[e], part[((size_t)e * BATCH + b) * DOPAD + n], s);
    out[i] = s;
}

// ---------------- launch ----------------
extern "C" void kernel_launch(void* const* d_in, const int* in_sizes, int n_in,
                              void* d_out, int out_size) {
    const float* x      = (const float*)d_in[0];
    const float* w1     = (const float*)d_in[1];
    const float* b1     = (const float*)d_in[2];
    const float* gamma1 = (const float*)d_in[3];
    const float* beta1  = (const float*)d_in[4];
    const float* w2     = (const float*)d_in[5];
    const float* b2     = (const float*)d_in[6];
    const float* gamma2 = (const float*)d_in[7];
    const float* beta2  = (const float*)d_in[8];
    const float* gw1    = (const float*)d_in[9];
    const float* gb1    = (const float*)d_in[10];
    const float* gw2    = (const float*)d_in[11];
    const float* gb2    = (const float*)d_in[12];
    const float* gw3    = (const float*)d_in[13];
    const float* gb3    = (const float*)d_in[14];
    const float* ew1    = (const float*)d_in[15];
    const float* eb1    = (const float*)d_in[16];
    const float* ew2    = (const float*)d_in[17];
    const float* eb2    = (const float*)d_in[18];
    const float* ew3    = (const float*)d_in[19];
    const float* eb3    = (const float*)d_in[20];

    float *p_xs, *p_enc1, *p_lat, *p_h1, *p_h2, *p_part, *p_w3p, *p_b3p;
    cudaGetSymbolAddress((void**)&p_xs,   g_xs);
    cudaGetSymbolAddress((void**)&p_enc1, g_enc1);
    cudaGetSymbolAddress((void**)&p_lat,  g_lat);
    cudaGetSymbolAddress((void**)&p_h1,   g_h1);
    cudaGetSymbolAddress((void**)&p_h2,   g_h2);
    cudaGetSymbolAddress((void**)&p_part, g_part);
    cudaGetSymbolAddress((void**)&p_w3p,  g_w3p);
    cudaGetSymbolAddress((void**)&p_b3p,  g_b3p);

    const int prepN = BATCH * XPAD + NE * HID * DOPAD + NE * DOPAD;
    prep_kernel<<<(prepN + 255) / 256, 256>>>(x, ew3, eb3);

    enc_bn_relu_kernel<DIN, XPAD, L1W><<<L1W, 256>>>(p_xs, w1, b1, gamma1, beta1, p_enc1);
    enc_bn_relu_kernel<L1W, L1W, L2W><<<L2W, 256>>>(p_enc1, w2, b2, gamma2, beta2, p_lat);

    gating_kernel<<<BATCH / 16, 256>>>(p_lat, gw1, gb1, gw2, gb2, gw3, gb3);

    // layer 1: xs[1024,128(pad)] x ew1[8,103,256]
    gen_expert_kernel<XPAD, XPAD, HID, DIN>
        <<<dim3(HID / 64, BATCH / 64, NE), 256>>>(p_xs, ew1, eb1, p_part);
    combine_vec_kernel<true><<<(BATCH * HID / 4 + 255) / 256, 256>>>(p_part, p_h1);

    // layer 2: h1[1024,256] x ew2[8,256,256]
    gen_expert_kernel<HID, HID, HID, HID>
        <<<dim3(HID / 64, BATCH / 64, NE), 256>>>(p_h1, ew2, eb2, p_part);
    combine_vec_kernel<true><<<(BATCH * HID / 4 + 255) / 256, 256>>>(p_part, p_h2);

    // layer 3: h2[1024,256] x w3p[8,256,64(pad)]
    gen_expert_kernel<HID, HID, DOPAD, HID>
        <<<dim3(1, BATCH / 64, NE), 256>>>(p_h2, p_w3p, p_b3p, p_part);
    combine_final_kernel<<<(BATCH * DOUT + 255) / 256, 256>>>(p_part, (float*)d_out);
}

// round 6
// speedup vs baseline: 1.8794x; 1.5870x over previous
#include <cuda_runtime.h>
#include <math.h>
#include <stdint.h>

#define BATCH 1024
#define DIN 103
#define XPAD 128
#define L1W 64
#define L2W 32
#define NE 8
#define GHW 64
#define HID 256
#define DOUT 51
#define DOPAD 64

// ---------------- scratch ----------------
__device__ float g_xs[BATCH * XPAD];          // padded input (zeros beyond 103)
__device__ float g_enc1[BATCH * L1W];
__device__ float g_lat[BATCH * L2W];
__device__ float g_bc[BATCH * NE];
__device__ float g_h1[BATCH * HID];
__device__ float g_h2[BATCH * HID];
__device__ float g_w3p[NE * HID * DOPAD];     // ew3 padded 51->64
__device__ float g_b3p[NE * DOPAD];
__device__ float g_part[NE * BATCH * HID];    // per-expert partials

// ---------------- prep: scale+pad xs, pad ew3/eb3 ----------------
__global__ void prep_kernel(const float* __restrict__ x,
                            const float* __restrict__ ew3,
                            const float* __restrict__ eb3) {
    int i = blockIdx.x * 256 + threadIdx.x;
    const int N1 = BATCH * XPAD;
    const int N2 = NE * HID * DOPAD;
    if (i < N1) {
        int b = i >> 7, c = i & 127;
        float v = 0.f;
        if (c < DIN) {
            v = x[b * DIN + c];
            if (c >= 100) v *= 100.0f;
        }
        g_xs[i] = v;
    } else if (i < N1 + N2) {
        int j = i - N1;
        int c = j & 63;
        int er = j >> 6;
        g_w3p[j] = (c < DOUT) ? ew3[er * DOUT + c] : 0.f;
    } else if (i < N1 + N2 + NE * DOPAD) {
        int j = i - N1 - N2;
        int e = j >> 6, c = j & 63;
        g_b3p[j] = (c < DOUT) ? eb3[e * DOUT + c] : 0.f;
    }
}

// ---------------- encoder: Linear + batch BN + ReLU, one block per feature ----------------
// IN4 = padded input width / 4 (float4 iterations), INREAL = true input dim
template <int IN4, int INREAL, int SIN, int SOUT>
__global__ __launch_bounds__(256)
void enc_bn_relu_kernel(const float* __restrict__ in,
                        const float* __restrict__ w, const float* __restrict__ b,
                        const float* __restrict__ gamma, const float* __restrict__ beta,
                        float* __restrict__ out) {
    const int f = blockIdx.x;
    __shared__ __align__(16) float wf[IN4 * 4];
    __shared__ float red[18];
    const int t = threadIdx.x;
    if (t < IN4 * 4) wf[t] = (t < INREAL) ? w[f * INREAL + t] : 0.f;
    __syncthreads();

    const float bf = b[f];
    float z[4];
    float s = 0.f, s2 = 0.f;
#pragma unroll
    for (int r = 0; r < 4; r++) {
        int row = t + 256 * r;
        const float4* xr = (const float4*)(in + (size_t)row * SIN);
        const float4* wv = (const float4*)wf;
        float acc = 0.f;
#pragma unroll 8
        for (int i = 0; i < IN4; i++) {
            float4 xv = xr[i];
            float4 ww = wv[i];
            acc = fmaf(xv.x, ww.x, acc);
            acc = fmaf(xv.y, ww.y, acc);
            acc = fmaf(xv.z, ww.z, acc);
            acc = fmaf(xv.w, ww.w, acc);
        }
        acc += bf;
        z[r] = acc;
        s += acc;
        s2 = fmaf(acc, acc, s2);
    }
#pragma unroll
    for (int o = 16; o > 0; o >>= 1) {
        s  += __shfl_xor_sync(0xFFFFFFFFu, s,  o);
        s2 += __shfl_xor_sync(0xFFFFFFFFu, s2, o);
    }
    int warp = t >> 5, lane = t & 31;
    if (lane == 0) { red[warp] = s; red[8 + warp] = s2; }
    __syncthreads();
    if (t == 0) {
        float S = 0.f, S2 = 0.f;
        for (int i = 0; i < 8; i++) { S += red[i]; S2 += red[8 + i]; }
        float mean = S * (1.0f / BATCH);
        float var  = S2 * (1.0f / BATCH) - mean * mean;
        float sc = gamma[f] * rsqrtf(var + 1e-5f);
        red[16] = sc;
        red[17] = beta[f] - mean * sc;
    }
    __syncthreads();
    float sc = red[16], sh = red[17];
#pragma unroll
    for (int r = 0; r < 4; r++) {
        int row = t + 256 * r;
        out[(size_t)row * SOUT + f] = fmaxf(fmaf(z[r], sc, sh), 0.f);
    }
}

// ---------------- gating MLP: 8 rows/block, 128 blocks, float4 weight staging ----------------
__global__ __launch_bounds__(256)
void gating_kernel(const float* __restrict__ lat,
                   const float* __restrict__ gw1, const float* __restrict__ gb1,
                   const float* __restrict__ gw2, const float* __restrict__ gb2,
                   const float* __restrict__ gw3, const float* __restrict__ gb3) {
    __shared__ float s_gw1[L2W * 65];      // [k][o] padded
    __shared__ float s_gw2[GHW * 65];      // [k][o] padded
    __shared__ float s_gw3[GHW * NE];      // [k][e]
    __shared__ float s_gb1[GHW], s_gb2[GHW], s_gb3[NE];
    __shared__ float s_lat[8][L2W];
    __shared__ float s_a1[8][GHW];
    __shared__ float s_a2[8][GHW];
    __shared__ float s_lg[8][NE];

    const int tid = threadIdx.x;
    const int b0 = blockIdx.x * 8;

    // gw1 [64][32] -> s_gw1[k][o], vectorized over k
#pragma unroll
    for (int j = 0; j < 2; j++) {
        int f = tid + 256 * j;             // 0..511 float4 index
        int o = f >> 3, kq = (f & 7) * 4;
        float4 v = ((const float4*)gw1)[f];
        s_gw1[(kq + 0) * 65 + o] = v.x;
        s_gw1[(kq + 1) * 65 + o] = v.y;
        s_gw1[(kq + 2) * 65 + o] = v.z;
        s_gw1[(kq + 3) * 65 + o] = v.w;
    }
    // gw2 [64][64] -> s_gw2[k][o]
#pragma unroll
    for (int j = 0; j < 4; j++) {
        int f = tid + 256 * j;             // 0..1023
        int o = f >> 4, kq = (f & 15) * 4;
        float4 v = ((const float4*)gw2)[f];
        s_gw2[(kq + 0) * 65 + o] = v.x;
        s_gw2[(kq + 1) * 65 + o] = v.y;
        s_gw2[(kq + 2) * 65 + o] = v.z;
        s_gw2[(kq + 3) * 65 + o] = v.w;
    }
    // gw3 [8][64] -> s_gw3[k][e]
    if (tid < 128) {
        int e = tid >> 4, kq = (tid & 15) * 4;
        float4 v = ((const float4*)gw3)[tid];
        s_gw3[(kq + 0) * NE + e] = v.x;
        s_gw3[(kq + 1) * NE + e] = v.y;
        s_gw3[(kq + 2) * NE + e] = v.z;
        s_gw3[(kq + 3) * NE + e] = v.w;
    }
    if (tid < GHW) { s_gb1[tid] = gb1[tid]; s_gb2[tid] = gb2[tid]; }
    if (tid >= 64 && tid < 64 + NE) s_gb3[tid - 64] = gb3[tid - 64];
    if (tid >= 128 && tid < 192) {
        int u = tid - 128;
        int r = u >> 3, kq = (u & 7) * 4;
        float4 v = *(const float4*)(lat + (size_t)(b0 + r) * L2W + kq);
        s_lat[r][kq + 0] = v.x; s_lat[r][kq + 1] = v.y;
        s_lat[r][kq + 2] = v.z; s_lat[r][kq + 3] = v.w;
    }
    __syncthreads();

    const int ox = tid & 63;
    const int rg = tid >> 6;               // 0..3 -> rows rg*2, rg*2+1
    const int r0 = rg * 2, r1 = rg * 2 + 1;

    // layer 1: 32 -> 64, ELU
    {
        float a0 = s_gb1[ox], a1 = s_gb1[ox];
#pragma unroll
        for (int k = 0; k < L2W; k++) {
            float w = s_gw1[k * 65 + ox];
            a0 = fmaf(s_lat[r0][k], w, a0);
            a1 = fmaf(s_lat[r1][k], w, a1);
        }
        s_a1[r0][ox] = (a0 > 0.f) ? a0 : expm1f(a0);
        s_a1[r1][ox] = (a1 > 0.f) ? a1 : expm1f(a1);
    }
    __syncthreads();

    // layer 2: 64 -> 64, ELU
    {
        float a0 = s_gb2[ox], a1 = s_gb2[ox];
#pragma unroll
        for (int k = 0; k < GHW; k++) {
            float w = s_gw2[k * 65 + ox];
            a0 = fmaf(s_a1[r0][k], w, a0);
            a1 = fmaf(s_a1[r1][k], w, a1);
        }
        s_a2[r0][ox] = (a0 > 0.f) ? a0 : expm1f(a0);
        s_a2[r1][ox] = (a1 > 0.f) ? a1 : expm1f(a1);
    }
    __syncthreads();

    // layer 3: 64 -> 8 logits
    if (tid < 64) {
        int e = tid & 7, r = tid >> 3;
        float acc = s_gb3[e];
#pragma unroll
        for (int k = 0; k < GHW; k++) acc = fmaf(s_a2[r][k], s_gw3[k * NE + e], acc);
        s_lg[r][e] = acc;
    }
    __syncthreads();

    // softmax per row
    if (tid < 8) {
        float m = s_lg[tid][0];
#pragma unroll
        for (int e = 1; e < NE; e++) m = fmaxf(m, s_lg[tid][e]);
        float ex[NE];
        float ssum = 0.f;
#pragma unroll
        for (int e = 0; e < NE; e++) { ex[e] = expf(s_lg[tid][e] - m); ssum += ex[e]; }
        float inv = 1.0f / ssum;
#pragma unroll
        for (int e = 0; e < NE; e++) g_bc[(size_t)(b0 + tid) * NE + e] = ex[e] * inv;
    }
}

// ---------------- generator layer GEMM: per-expert, BN=64, TN=4, templated BM/TM ----------------
// part[e][b][n] = sum_k A[b][k] * W[e][k][n] + bias[e][n]
template <int KSIZE, int ASTRIDE, int OUTN, int INREAL, int BM, int TM>
__global__ __launch_bounds__(256)
void gen_expert_kernel(const float* __restrict__ A,
                       const float* __restrict__ W,
                       const float* __restrict__ bias,
                       float* __restrict__ part) {
    constexpr int BN = 64, BK = 32;
    constexpr int KT = KSIZE / BK;
    constexpr int F4PT = BM * BK / 1024;   // float4 A-loads per thread
    __shared__ __align__(16) float As[BK][BM + 4];
    __shared__ __align__(16) float Ws[BK][BN];
    __shared__ float sbias[BN];

    const int e  = blockIdx.z;
    const int m0 = blockIdx.y * BM;
    const int n0 = blockIdx.x * BN;
    const int tid = threadIdx.x;
    const int tx = tid & 15;               // n-subtile
    const int ty = tid >> 4;               // m-subtile

    // W tile load map: 32x64 floats = 512 float4; 2 per thread
    const int wk = tid >> 3;
    const int wc = (tid & 7) * 8;

    const float* Wbase = W + (size_t)e * INREAL * OUTN;
    if (tid < BN) sbias[tid] = bias[(size_t)e * OUTN + n0 + tid];

    float acc[TM][4];
#pragma unroll
    for (int i = 0; i < TM; i++)
#pragma unroll
        for (int j = 0; j < 4; j++) acc[i][j] = 0.f;

    for (int kt = 0; kt < KT; kt++) {
        const int k0 = kt * BK;
        __syncthreads();
        // A tile, transpose on store
#pragma unroll
        for (int j = 0; j < F4PT; j++) {
            int idx = tid * F4PT + j;          // float4 index over [BM][BK/4]
            int r = idx >> 3;
            int kq = (idx & 7) * 4;
            float4 v = *(const float4*)(A + (size_t)(m0 + r) * ASTRIDE + k0 + kq);
            As[kq + 0][r] = v.x;
            As[kq + 1][r] = v.y;
            As[kq + 2][r] = v.z;
            As[kq + 3][r] = v.w;
        }
        // W tile
        {
            int gk = k0 + wk;
            if (KSIZE != INREAL) gk = (gk < INREAL) ? gk : (INREAL - 1);
            const float* wp = Wbase + (size_t)gk * OUTN + n0;
            *(float4*)&Ws[wk][wc]     = *(const float4*)(wp + wc);
            *(float4*)&Ws[wk][wc + 4] = *(const float4*)(wp + wc + 4);
        }
        __syncthreads();
#pragma unroll 8
        for (int k = 0; k < BK; k++) {
            float4 w = *(const float4*)&Ws[k][tx * 4];
#pragma unroll
            for (int i4 = 0; i4 < TM / 4; i4++) {
                float4 a = *(const float4*)&As[k][ty * TM + i4 * 4];
                acc[i4 * 4 + 0][0] = fmaf(a.x, w.x, acc[i4 * 4 + 0][0]);
                acc[i4 * 4 + 0][1] = fmaf(a.x, w.y, acc[i4 * 4 + 0][1]);
                acc[i4 * 4 + 0][2] = fmaf(a.x, w.z, acc[i4 * 4 + 0][2]);
                acc[i4 * 4 + 0][3] = fmaf(a.x, w.w, acc[i4 * 4 + 0][3]);
                acc[i4 * 4 + 1][0] = fmaf(a.y, w.x, acc[i4 * 4 + 1][0]);
                acc[i4 * 4 + 1][1] = fmaf(a.y, w.y, acc[i4 * 4 + 1][1]);
                acc[i4 * 4 + 1][2] = fmaf(a.y, w.z, acc[i4 * 4 + 1][2]);
                acc[i4 * 4 + 1][3] = fmaf(a.y, w.w, acc[i4 * 4 + 1][3]);
                acc[i4 * 4 + 2][0] = fmaf(a.z, w.x, acc[i4 * 4 + 2][0]);
                acc[i4 * 4 + 2][1] = fmaf(a.z, w.y, acc[i4 * 4 + 2][1]);
                acc[i4 * 4 + 2][2] = fmaf(a.z, w.z, acc[i4 * 4 + 2][2]);
                acc[i4 * 4 + 2][3] = fmaf(a.z, w.w, acc[i4 * 4 + 2][3]);
                acc[i4 * 4 + 3][0] = fmaf(a.w, w.x, acc[i4 * 4 + 3][0]);
                acc[i4 * 4 + 3][1] = fmaf(a.w, w.y, acc[i4 * 4 + 3][1]);
                acc[i4 * 4 + 3][2] = fmaf(a.w, w.z, acc[i4 * 4 + 3][2]);
                acc[i4 * 4 + 3][3] = fmaf(a.w, w.w, acc[i4 * 4 + 3][3]);
            }
        }
    }

#pragma unroll
    for (int i = 0; i < TM; i++) {
        const int row = m0 + ty * TM + i;
        float* pp = part + ((size_t)e * BATCH + row) * OUTN + n0 + tx * 4;
        float4 o;
        o.x = acc[i][0] + sbias[tx * 4 + 0];
        o.y = acc[i][1] + sbias[tx * 4 + 1];
        o.z = acc[i][2] + sbias[tx * 4 + 2];
        o.w = acc[i][3] + sbias[tx * 4 + 3];
        *(float4*)pp = o;
    }
}

// ---------------- combine experts with bc weights (+ optional ELU), vectorized ----------------
template <bool ACT>
__global__ void combine_vec_kernel(const float* __restrict__ part, float* __restrict__ out) {
    const int i = blockIdx.x * 256 + threadIdx.x;       // float4 lanes over [B][64]
    if (i >= BATCH * (HID / 4)) return;
    const int b = i >> 6;
    const float* bcp = g_bc + (size_t)b * NE;
    float4 s = make_float4(0.f, 0.f, 0.f, 0.f);
#pragma unroll
    for (int e = 0; e < NE; e++) {
        float c = bcp[e];
        float4 p = ((const float4*)part)[(size_t)e * BATCH * (HID / 4) + i];
        s.x = fmaf(c, p.x, s.x);
        s.y = fmaf(c, p.y, s.y);
        s.z = fmaf(c, p.z, s.z);
        s.w = fmaf(c, p.w, s.w);
    }
    if (ACT) {
        s.x = (s.x > 0.f) ? s.x : expm1f(s.x);
        s.y = (s.y > 0.f) ? s.y : expm1f(s.y);
        s.z = (s.z > 0.f) ? s.z : expm1f(s.z);
        s.w = (s.w > 0.f) ? s.w : expm1f(s.w);
    }
    ((float4*)out)[i] = s;
}

// final combine: padded stride 64 -> write 51
__global__ void combine_final_kernel(const float* __restrict__ part, float* __restrict__ out) {
    const int i = blockIdx.x * 256 + threadIdx.x;
    if (i >= BATCH * DOUT) return;
    const int b = i / DOUT;
    const int n = i - b * DOUT;
    const float* bcp = g_bc + (size_t)b * NE;
    float s = 0.f;
#pragma unroll
    for (int e = 0; e < NE; e++)
        s = fmaf(bcp[e], part[((size_t)e * BATCH + b) * DOPAD + n], s);
    out[i] = s;
}

// ---------------- launch ----------------
extern "C" void kernel_launch(void* const* d_in, const int* in_sizes, int n_in,
                              void* d_out, int out_size) {
    const float* x      = (const float*)d_in[0];
    const float* w1     = (const float*)d_in[1];
    const float* b1     = (const float*)d_in[2];
    const float* gamma1 = (const float*)d_in[3];
    const float* beta1  = (const float*)d_in[4];
    const float* w2     = (const float*)d_in[5];
    const float* b2     = (const float*)d_in[6];
    const float* gamma2 = (const float*)d_in[7];
    const float* beta2  = (const float*)d_in[8];
    const float* gw1    = (const float*)d_in[9];
    const float* gb1    = (const float*)d_in[10];
    const float* gw2    = (const float*)d_in[11];
    const float* gb2    = (const float*)d_in[12];
    const float* gw3    = (const float*)d_in[13];
    const float* gb3    = (const float*)d_in[14];
    const float* ew1    = (const float*)d_in[15];
    const float* eb1    = (const float*)d_in[16];
    const float* ew2    = (const float*)d_in[17];
    const float* eb2    = (const float*)d_in[18];
    const float* ew3    = (const float*)d_in[19];
    const float* eb3    = (const float*)d_in[20];

    float *p_xs, *p_enc1, *p_lat, *p_h1, *p_h2, *p_part, *p_w3p, *p_b3p;
    cudaGetSymbolAddress((void**)&p_xs,   g_xs);
    cudaGetSymbolAddress((void**)&p_enc1, g_enc1);
    cudaGetSymbolAddress((void**)&p_lat,  g_lat);
    cudaGetSymbolAddress((void**)&p_h1,   g_h1);
    cudaGetSymbolAddress((void**)&p_h2,   g_h2);
    cudaGetSymbolAddress((void**)&p_part, g_part);
    cudaGetSymbolAddress((void**)&p_w3p,  g_w3p);
    cudaGetSymbolAddress((void**)&p_b3p,  g_b3p);

    const int prepN = BATCH * XPAD + NE * HID * DOPAD + NE * DOPAD;
    prep_kernel<<<(prepN + 255) / 256, 256>>>(x, ew3, eb3);

    enc_bn_relu_kernel<32, DIN, XPAD, L1W><<<L1W, 256>>>(p_xs, w1, b1, gamma1, beta1, p_enc1);
    enc_bn_relu_kernel<16, L1W, L1W, L2W><<<L2W, 256>>>(p_enc1, w2, b2, gamma2, beta2, p_lat);

    gating_kernel<<<BATCH / 8, 256>>>(p_lat, gw1, gb1, gw2, gb2, gw3, gb3);

    // layer 1: xs[1024,128(pad)] x ew1[8,103,256]  BM=128, TM=8
    gen_expert_kernel<XPAD, XPAD, HID, DIN, 128, 8>
        <<<dim3(HID / 64, BATCH / 128, NE), 256>>>(p_xs, ew1, eb1, p_part);
    combine_vec_kernel<true><<<(BATCH * HID / 4 + 255) / 256, 256>>>(p_part, p_h1);

    // layer 2: h1[1024,256] x ew2[8,256,256]  BM=128, TM=8
    gen_expert_kernel<HID, HID, HID, HID, 128, 8>
        <<<dim3(HID / 64, BATCH / 128, NE), 256>>>(p_h1, ew2, eb2, p_part);
    combine_vec_kernel<true><<<(BATCH * HID / 4 + 255) / 256, 256>>>(p_part, p_h2);

    // layer 3: h2[1024,256] x w3p[8,256,64(pad)]  BM=64, TM=4 -> 128 blocks
    gen_expert_kernel<HID, HID, DOPAD, HID, 64, 4>
        <<<dim3(1, BATCH / 64, NE), 256>>>(p_h2, p_w3p, p_b3p, p_part);
    combine_final_kernel<<<(BATCH * DOUT + 255) / 256, 256>>>(p_part, (float*)d_out);
}

// round 7
// speedup vs baseline: 1.9758x; 1.0513x over previous
#include <cuda_runtime.h>
#include <math.h>
#include <stdint.h>

#define BATCH 1024
#define DIN 103
#define XPAD 128
#define L1W 64
#define L2W 32
#define NE 8
#define GHW 64
#define HID 256
#define DOUT 51
#define DOPAD 64

// ---------------- scratch ----------------
__device__ float g_xs[BATCH * XPAD];          // padded input (zeros beyond 103)
__device__ float g_enc1[BATCH * L1W];
__device__ float g_lat[BATCH * L2W];
__device__ float g_bc[BATCH * NE];
__device__ float g_h1[BATCH * HID];
__device__ float g_h2[BATCH * HID];
__device__ float g_w3p[NE * HID * DOPAD];     // ew3 padded 51->64
__device__ float g_b3p[NE * DOPAD];
__device__ float g_part[NE * BATCH * HID];    // per-expert partials

// ---------------- prep: scale+pad xs, pad ew3/eb3 ----------------
__global__ void prep_kernel(const float* __restrict__ x,
                            const float* __restrict__ ew3,
                            const float* __restrict__ eb3) {
    int i = blockIdx.x * 256 + threadIdx.x;
    const int N1 = BATCH * XPAD;
    const int N2 = NE * HID * DOPAD;
    if (i < N1) {
        int b = i >> 7, c = i & 127;
        float v = 0.f;
        if (c < DIN) {
            v = x[b * DIN + c];
            if (c >= 100) v *= 100.0f;
        }
        g_xs[i] = v;
    } else if (i < N1 + N2) {
        int j = i - N1;
        int c = j & 63;
        int er = j >> 6;
        g_w3p[j] = (c < DOUT) ? ew3[er * DOUT + c] : 0.f;
    } else if (i < N1 + N2 + NE * DOPAD) {
        int j = i - N1 - N2;
        int e = j >> 6, c = j & 63;
        g_b3p[j] = (c < DOUT) ? eb3[e * DOUT + c] : 0.f;
    }
}

// ---------------- encoder: Linear + batch BN + ReLU, one block per feature ----------------
template <int IN4, int INREAL, int SIN, int SOUT>
__global__ __launch_bounds__(256)
void enc_bn_relu_kernel(const float* __restrict__ in,
                        const float* __restrict__ w, const float* __restrict__ b,
                        const float* __restrict__ gamma, const float* __restrict__ beta,
                        float* __restrict__ out) {
    const int f = blockIdx.x;
    __shared__ __align__(16) float wf[IN4 * 4];
    __shared__ float red[18];
    const int t = threadIdx.x;
    if (t < IN4 * 4) wf[t] = (t < INREAL) ? w[f * INREAL + t] : 0.f;
    __syncthreads();

    const float bf = b[f];
    float z[4];
    float s = 0.f, s2 = 0.f;
#pragma unroll
    for (int r = 0; r < 4; r++) {
        int row = t + 256 * r;
        const float4* xr = (const float4*)(in + (size_t)row * SIN);
        const float4* wv = (const float4*)wf;
        float acc = 0.f;
#pragma unroll 8
        for (int i = 0; i < IN4; i++) {
            float4 xv = xr[i];
            float4 ww = wv[i];
            acc = fmaf(xv.x, ww.x, acc);
            acc = fmaf(xv.y, ww.y, acc);
            acc = fmaf(xv.z, ww.z, acc);
            acc = fmaf(xv.w, ww.w, acc);
        }
        acc += bf;
        z[r] = acc;
        s += acc;
        s2 = fmaf(acc, acc, s2);
    }
#pragma unroll
    for (int o = 16; o > 0; o >>= 1) {
        s  += __shfl_xor_sync(0xFFFFFFFFu, s,  o);
        s2 += __shfl_xor_sync(0xFFFFFFFFu, s2, o);
    }
    int warp = t >> 5, lane = t & 31;
    if (lane == 0) { red[warp] = s; red[8 + warp] = s2; }
    __syncthreads();
    if (t == 0) {
        float S = 0.f, S2 = 0.f;
        for (int i = 0; i < 8; i++) { S += red[i]; S2 += red[8 + i]; }
        float mean = S * (1.0f / BATCH);
        float var  = S2 * (1.0f / BATCH) - mean * mean;
        float sc = gamma[f] * rsqrtf(var + 1e-5f);
        red[16] = sc;
        red[17] = beta[f] - mean * sc;
    }
    __syncthreads();
    float sc = red[16], sh = red[17];
#pragma unroll
    for (int r = 0; r < 4; r++) {
        int row = t + 256 * r;
        out[(size_t)row * SOUT + f] = fmaxf(fmaf(z[r], sc, sh), 0.f);
    }
}

// ---------------- gating MLP: 8 rows/block, 128 blocks, float4 weight staging ----------------
__global__ __launch_bounds__(256)
void gating_kernel(const float* __restrict__ lat,
                   const float* __restrict__ gw1, const float* __restrict__ gb1,
                   const float* __restrict__ gw2, const float* __restrict__ gb2,
                   const float* __restrict__ gw3, const float* __restrict__ gb3) {
    __shared__ float s_gw1[L2W * 65];
    __shared__ float s_gw2[GHW * 65];
    __shared__ float s_gw3[GHW * NE];
    __shared__ float s_gb1[GHW], s_gb2[GHW], s_gb3[NE];
    __shared__ float s_lat[8][L2W];
    __shared__ float s_a1[8][GHW];
    __shared__ float s_a2[8][GHW];
    __shared__ float s_lg[8][NE];

    const int tid = threadIdx.x;
    const int b0 = blockIdx.x * 8;

#pragma unroll
    for (int j = 0; j < 2; j++) {
        int f = tid + 256 * j;
        int o = f >> 3, kq = (f & 7) * 4;
        float4 v = ((const float4*)gw1)[f];
        s_gw1[(kq + 0) * 65 + o] = v.x;
        s_gw1[(kq + 1) * 65 + o] = v.y;
        s_gw1[(kq + 2) * 65 + o] = v.z;
        s_gw1[(kq + 3) * 65 + o] = v.w;
    }
#pragma unroll
    for (int j = 0; j < 4; j++) {
        int f = tid + 256 * j;
        int o = f >> 4, kq = (f & 15) * 4;
        float4 v = ((const float4*)gw2)[f];
        s_gw2[(kq + 0) * 65 + o] = v.x;
        s_gw2[(kq + 1) * 65 + o] = v.y;
        s_gw2[(kq + 2) * 65 + o] = v.z;
        s_gw2[(kq + 3) * 65 + o] = v.w;
    }
    if (tid < 128) {
        int e = tid >> 4, kq = (tid & 15) * 4;
        float4 v = ((const float4*)gw3)[tid];
        s_gw3[(kq + 0) * NE + e] = v.x;
        s_gw3[(kq + 1) * NE + e] = v.y;
        s_gw3[(kq + 2) * NE + e] = v.z;
        s_gw3[(kq + 3) * NE + e] = v.w;
    }
    if (tid < GHW) { s_gb1[tid] = gb1[tid]; s_gb2[tid] = gb2[tid]; }
    if (tid >= 64 && tid < 64 + NE) s_gb3[tid - 64] = gb3[tid - 64];
    if (tid >= 128 && tid < 192) {
        int u = tid - 128;
        int r = u >> 3, kq = (u & 7) * 4;
        float4 v = *(const float4*)(lat + (size_t)(b0 + r) * L2W + kq);
        s_lat[r][kq + 0] = v.x; s_lat[r][kq + 1] = v.y;
        s_lat[r][kq + 2] = v.z; s_lat[r][kq + 3] = v.w;
    }
    __syncthreads();

    const int ox = tid & 63;
    const int rg = tid >> 6;
    const int r0 = rg * 2, r1 = rg * 2 + 1;

    {
        float a0 = s_gb1[ox], a1 = s_gb1[ox];
#pragma unroll
        for (int k = 0; k < L2W; k++) {
            float w = s_gw1[k * 65 + ox];
            a0 = fmaf(s_lat[r0][k], w, a0);
            a1 = fmaf(s_lat[r1][k], w, a1);
        }
        s_a1[r0][ox] = (a0 > 0.f) ? a0 : expm1f(a0);
        s_a1[r1][ox] = (a1 > 0.f) ? a1 : expm1f(a1);
    }
    __syncthreads();

    {
        float a0 = s_gb2[ox], a1 = s_gb2[ox];
#pragma unroll
        for (int k = 0; k < GHW; k++) {
            float w = s_gw2[k * 65 + ox];
            a0 = fmaf(s_a1[r0][k], w, a0);
            a1 = fmaf(s_a1[r1][k], w, a1);
        }
        s_a2[r0][ox] = (a0 > 0.f) ? a0 : expm1f(a0);
        s_a2[r1][ox] = (a1 > 0.f) ? a1 : expm1f(a1);
    }
    __syncthreads();

    if (tid < 64) {
        int e = tid & 7, r = tid >> 3;
        float acc = s_gb3[e];
#pragma unroll
        for (int k = 0; k < GHW; k++) acc = fmaf(s_a2[r][k], s_gw3[k * NE + e], acc);
        s_lg[r][e] = acc;
    }
    __syncthreads();

    if (tid < 8) {
        float m = s_lg[tid][0];
#pragma unroll
        for (int e = 1; e < NE; e++) m = fmaxf(m, s_lg[tid][e]);
        float ex[NE];
        float ssum = 0.f;
#pragma unroll
        for (int e = 0; e < NE; e++) { ex[e] = expf(s_lg[tid][e] - m); ssum += ex[e]; }
        float inv = 1.0f / ssum;
#pragma unroll
        for (int e = 0; e < NE; e++) g_bc[(size_t)(b0 + tid) * NE + e] = ex[e] * inv;
    }
}

// ---------------- generator layer GEMM: double-buffered, register-prefetched ----------------
// part[e][b][n] = sum_k A[b][k] * W[e][k][n] + bias[e][n]
template <int KSIZE, int ASTRIDE, int OUTN, int INREAL, int BM, int TM>
__global__ __launch_bounds__(256)
void gen_expert_kernel(const float* __restrict__ A,
                       const float* __restrict__ W,
                       const float* __restrict__ bias,
                       float* __restrict__ part) {
    constexpr int BN = 64, BK = 32;
    constexpr int KT = KSIZE / BK;
    constexpr int F4A = BM * BK / 1024;    // float4 A-loads per thread (4 for BM=128, 2 for BM=64)
    __shared__ __align__(16) float As[2][BK][BM + 4];
    __shared__ __align__(16) float Ws[2][BK][BN];
    __shared__ float sbias[BN];

    const int e  = blockIdx.z;
    const int m0 = blockIdx.y * BM;
    const int n0 = blockIdx.x * BN;
    const int tid = threadIdx.x;
    const int tx = tid & 15;
    const int ty = tid >> 4;

    // A load map
    int a_r[F4A], a_kq[F4A];
#pragma unroll
    for (int j = 0; j < F4A; j++) {
        int idx = tid * F4A + j;
        a_r[j] = idx >> 3;
        a_kq[j] = (idx & 7) * 4;
    }
    // W load map: 32x64 floats = 512 float4; 2 per thread
    const int wk = tid >> 3;
    const int wc = (tid & 7) * 8;

    const float* Wbase = W + (size_t)e * INREAL * OUTN;
    if (tid < BN) sbias[tid] = bias[(size_t)e * OUTN + n0 + tid];

    float acc[TM][4];
#pragma unroll
    for (int i = 0; i < TM; i++)
#pragma unroll
        for (int j = 0; j < 4; j++) acc[i][j] = 0.f;

    float4 pa[F4A];
    float4 pw0, pw1;

    // prologue: load tile 0
    {
#pragma unroll
        for (int j = 0; j < F4A; j++)
            pa[j] = *(const float4*)(A + (size_t)(m0 + a_r[j]) * ASTRIDE + a_kq[j]);
        int gk = wk;
        if (KSIZE != INREAL) gk = (gk < INREAL) ? gk : (INREAL - 1);
        const float* wp = Wbase + (size_t)gk * OUTN + n0;
        pw0 = *(const float4*)(wp + wc);
        pw1 = *(const float4*)(wp + wc + 4);
    }
    // store tile 0 -> buf 0
    {
#pragma unroll
        for (int j = 0; j < F4A; j++) {
            As[0][a_kq[j] + 0][a_r[j]] = pa[j].x;
            As[0][a_kq[j] + 1][a_r[j]] = pa[j].y;
            As[0][a_kq[j] + 2][a_r[j]] = pa[j].z;
            As[0][a_kq[j] + 3][a_r[j]] = pa[j].w;
        }
        *(float4*)&Ws[0][wk][wc]     = pw0;
        *(float4*)&Ws[0][wk][wc + 4] = pw1;
    }
    __syncthreads();

    for (int kt = 0; kt < KT; kt++) {
        const int buf = kt & 1;
        // prefetch next tile into registers
        if (kt + 1 < KT) {
            const int k0 = (kt + 1) * BK;
#pragma unroll
            for (int j = 0; j < F4A; j++)
                pa[j] = *(const float4*)(A + (size_t)(m0 + a_r[j]) * ASTRIDE + k0 + a_kq[j]);
            int gk = k0 + wk;
            if (KSIZE != INREAL) gk = (gk < INREAL) ? gk : (INREAL - 1);
            const float* wp = Wbase + (size_t)gk * OUTN + n0;
            pw0 = *(const float4*)(wp + wc);
            pw1 = *(const float4*)(wp + wc + 4);
        }
        // compute current tile
#pragma unroll 8
        for (int k = 0; k < BK; k++) {
            float4 w = *(const float4*)&Ws[buf][k][tx * 4];
#pragma unroll
            for (int i4 = 0; i4 < TM / 4; i4++) {
                float4 a = *(const float4*)&As[buf][k][ty * TM + i4 * 4];
                acc[i4 * 4 + 0][0] = fmaf(a.x, w.x, acc[i4 * 4 + 0][0]);
                acc[i4 * 4 + 0][1] = fmaf(a.x, w.y, acc[i4 * 4 + 0][1]);
                acc[i4 * 4 + 0][2] = fmaf(a.x, w.z, acc[i4 * 4 + 0][2]);
                acc[i4 * 4 + 0][3] = fmaf(a.x, w.w, acc[i4 * 4 + 0][3]);
                acc[i4 * 4 + 1][0] = fmaf(a.y, w.x, acc[i4 * 4 + 1][0]);
                acc[i4 * 4 + 1][1] = fmaf(a.y, w.y, acc[i4 * 4 + 1][1]);
                acc[i4 * 4 + 1][2] = fmaf(a.y, w.z, acc[i4 * 4 + 1][2]);
                acc[i4 * 4 + 1][3] = fmaf(a.y, w.w, acc[i4 * 4 + 1][3]);
                acc[i4 * 4 + 2][0] = fmaf(a.z, w.x, acc[i4 * 4 + 2][0]);
                acc[i4 * 4 + 2][1] = fmaf(a.z, w.y, acc[i4 * 4 + 2][1]);
                acc[i4 * 4 + 2][2] = fmaf(a.z, w.z, acc[i4 * 4 + 2][2]);
                acc[i4 * 4 + 2][3] = fmaf(a.z, w.w, acc[i4 * 4 + 2][3]);
                acc[i4 * 4 + 3][0] = fmaf(a.w, w.x, acc[i4 * 4 + 3][0]);
                acc[i4 * 4 + 3][1] = fmaf(a.w, w.y, acc[i4 * 4 + 3][1]);
                acc[i4 * 4 + 3][2] = fmaf(a.w, w.z, acc[i4 * 4 + 3][2]);
                acc[i4 * 4 + 3][3] = fmaf(a.w, w.w, acc[i4 * 4 + 3][3]);
            }
        }
        // store prefetched tile -> other buffer
        if (kt + 1 < KT) {
            const int nb = buf ^ 1;
#pragma unroll
            for (int j = 0; j < F4A; j++) {
                As[nb][a_kq[j] + 0][a_r[j]] = pa[j].x;
                As[nb][a_kq[j] + 1][a_r[j]] = pa[j].y;
                As[nb][a_kq[j] + 2][a_r[j]] = pa[j].z;
                As[nb][a_kq[j] + 3][a_r[j]] = pa[j].w;
            }
            *(float4*)&Ws[nb][wk][wc]     = pw0;
            *(float4*)&Ws[nb][wk][wc + 4] = pw1;
            __syncthreads();
        }
    }

#pragma unroll
    for (int i = 0; i < TM; i++) {
        const int row = m0 + ty * TM + i;
        float* pp = part + ((size_t)e * BATCH + row) * OUTN + n0 + tx * 4;
        float4 o;
        o.x = acc[i][0] + sbias[tx * 4 + 0];
        o.y = acc[i][1] + sbias[tx * 4 + 1];
        o.z = acc[i][2] + sbias[tx * 4 + 2];
        o.w = acc[i][3] + sbias[tx * 4 + 3];
        *(float4*)pp = o;
    }
}

// ---------------- combine experts with bc weights (+ optional ELU), vectorized ----------------
template <bool ACT>
__global__ void combine_vec_kernel(const float* __restrict__ part, float* __restrict__ out) {
    const int i = blockIdx.x * 256 + threadIdx.x;
    if (i >= BATCH * (HID / 4)) return;
    const int b = i >> 6;
    const float* bcp = g_bc + (size_t)b * NE;
    float4 s = make_float4(0.f, 0.f, 0.f, 0.f);
#pragma unroll
    for (int e = 0; e < NE; e++) {
        float c = bcp[e];
        float4 p = ((const float4*)part)[(size_t)e * BATCH * (HID / 4) + i];
        s.x = fmaf(c, p.x, s.x);
        s.y = fmaf(c, p.y, s.y);
        s.z = fmaf(c, p.z, s.z);
        s.w = fmaf(c, p.w, s.w);
    }
    if (ACT) {
        s.x = (s.x > 0.f) ? s.x : expm1f(s.x);
        s.y = (s.y > 0.f) ? s.y : expm1f(s.y);
        s.z = (s.z > 0.f) ? s.z : expm1f(s.z);
        s.w = (s.w > 0.f) ? s.w : expm1f(s.w);
    }
    ((float4*)out)[i] = s;
}

// final combine: padded stride 64 -> write 51
__global__ void combine_final_kernel(const float* __restrict__ part, float* __restrict__ out) {
    const int i = blockIdx.x * 256 + threadIdx.x;
    if (i >= BATCH * DOUT) return;
    const int b = i / DOUT;
    const int n = i - b * DOUT;
    const float* bcp = g_bc + (size_t)b * NE;
    float s = 0.f;
#pragma unroll
    for (int e = 0; e < NE; e++)
        s = fmaf(bcp[e], part[((size_t)e * BATCH + b) * DOPAD + n], s);
    out[i] = s;
}

// ---------------- launch ----------------
extern "C" void kernel_launch(void* const* d_in, const int* in_sizes, int n_in,
                              void* d_out, int out_size) {
    const float* x      = (const float*)d_in[0];
    const float* w1     = (const float*)d_in[1];
    const float* b1     = (const float*)d_in[2];
    const float* gamma1 = (const float*)d_in[3];
    const float* beta1  = (const float*)d_in[4];
    const float* w2     = (const float*)d_in[5];
    const float* b2     = (const float*)d_in[6];
    const float* gamma2 = (const float*)d_in[7];
    const float* beta2  = (const float*)d_in[8];
    const float* gw1    = (const float*)d_in[9];
    const float* gb1    = (const float*)d_in[10];
    const float* gw2    = (const float*)d_in[11];
    const float* gb2    = (const float*)d_in[12];
    const float* gw3    = (const float*)d_in[13];
    const float* gb3    = (const float*)d_in[14];
    const float* ew1    = (const float*)d_in[15];
    const float* eb1    = (const float*)d_in[16];
    const float* ew2    = (const float*)d_in[17];
    const float* eb2    = (const float*)d_in[18];
    const float* ew3    = (const float*)d_in[19];
    const float* eb3    = (const float*)d_in[20];

    float *p_xs, *p_enc1, *p_lat, *p_h1, *p_h2, *p_part, *p_w3p, *p_b3p;
    cudaGetSymbolAddress((void**)&p_xs,   g_xs);
    cudaGetSymbolAddress((void**)&p_enc1, g_enc1);
    cudaGetSymbolAddress((void**)&p_lat,  g_lat);
    cudaGetSymbolAddress((void**)&p_h1,   g_h1);
    cudaGetSymbolAddress((void**)&p_h2,   g_h2);
    cudaGetSymbolAddress((void**)&p_part, g_part);
    cudaGetSymbolAddress((void**)&p_w3p,  g_w3p);
    cudaGetSymbolAddress((void**)&p_b3p,  g_b3p);

    const int prepN = BATCH * XPAD + NE * HID * DOPAD + NE * DOPAD;
    prep_kernel<<<(prepN + 255) / 256, 256>>>(x, ew3, eb3);

    enc_bn_relu_kernel<32, DIN, XPAD, L1W><<<L1W, 256>>>(p_xs, w1, b1, gamma1, beta1, p_enc1);
    enc_bn_relu_kernel<16, L1W, L1W, L2W><<<L2W, 256>>>(p_enc1, w2, b2, gamma2, beta2, p_lat);

    gating_kernel<<<BATCH / 8, 256>>>(p_lat, gw1, gb1, gw2, gb2, gw3, gb3);

    // layer 1: xs[1024,128(pad)] x ew1[8,103,256]  BM=128, TM=8
    gen_expert_kernel<XPAD, XPAD, HID, DIN, 128, 8>
        <<<dim3(HID / 64, BATCH / 128, NE), 256>>>(p_xs, ew1, eb1, p_part);
    combine_vec_kernel<true><<<(BATCH * HID / 4 + 255) / 256, 256>>>(p_part, p_h1);

    // layer 2: h1[1024,256] x ew2[8,256,256]  BM=128, TM=8
    gen_expert_kernel<HID, HID, HID, HID, 128, 8>
        <<<dim3(HID / 64, BATCH / 128, NE), 256>>>(p_h1, ew2, eb2, p_part);
    combine_vec_kernel<true><<<(BATCH * HID / 4 + 255) / 256, 256>>>(p_part, p_h2);

    // layer 3: h2[1024,256] x w3p[8,256,64(pad)]  BM=64, TM=4 -> 128 blocks
    gen_expert_kernel<HID, HID, DOPAD, HID, 64, 4>
        <<<dim3(1, BATCH / 64, NE), 256>>>(p_h2, p_w3p, p_b3p, p_part);
    combine_final_kernel<<<(BATCH * DOUT + 255) / 256, 256>>>(p_part, (float*)d_out);
}

// round 9
// speedup vs baseline: 2.0223x; 1.0235x over previous
#include <cuda_runtime.h>
#include <math.h>
#include <stdint.h>

#define BATCH 1024
#define DIN 103
#define XPAD 128
#define L1W 64
#define L2W 32
#define NE 8
#define GHW 64
#define HID 256
#define DOUT 51
#define DOPAD 64

typedef unsigned long long u64;

// ---------------- scratch ----------------
__device__ float g_xs[BATCH * XPAD];          // padded input (zeros beyond 103)
__device__ float g_enc1[BATCH * L1W];
__device__ float g_lat[BATCH * L2W];
__device__ float g_bc[BATCH * NE];
__device__ float g_h1[BATCH * HID];
__device__ float g_h2[BATCH * HID];
__device__ float g_w3p[NE * HID * DOPAD];     // ew3 padded 51->64
__device__ float g_b3p[NE * DOPAD];
__device__ float g_part[NE * BATCH * HID];    // per-expert partials

// packed fp32x2 FMA (sm_100+): two independent fp32 FMAs in one fma-pipe instr
__device__ __forceinline__ u64 ffma2(u64 a, u64 b, u64 c) {
    u64 d;
    asm("fma.rn.f32x2 %0, %1, %2, %3;" : "=l"(d) : "l"(a), "l"(b), "l"(c));
    return d;
}
__device__ __forceinline__ u64 fadd2(u64 a, u64 b) {
    u64 d;
    asm("add.rn.f32x2 %0, %1, %2;" : "=l"(d) : "l"(a), "l"(b));
    return d;
}

// ---------------- prep: scale+pad xs, pad ew3/eb3 ----------------
__global__ void prep_kernel(const float* __restrict__ x,
                            const float* __restrict__ ew3,
                            const float* __restrict__ eb3) {
    int i = blockIdx.x * 256 + threadIdx.x;
    const int N1 = BATCH * XPAD;
    const int N2 = NE * HID * DOPAD;
    if (i < N1) {
        int b = i >> 7, c = i & 127;
        float v = 0.f;
        if (c < DIN) {
            v = x[b * DIN + c];
            if (c >= 100) v *= 100.0f;
        }
        g_xs[i] = v;
    } else if (i < N1 + N2) {
        int j = i - N1;
        int c = j & 63;
        int er = j >> 6;
        g_w3p[j] = (c < DOUT) ? ew3[er * DOUT + c] : 0.f;
    } else if (i < N1 + N2 + NE * DOPAD) {
        int j = i - N1 - N2;
        int e = j >> 6, c = j & 63;
        g_b3p[j] = (c < DOUT) ? eb3[e * DOUT + c] : 0.f;
    }
}

// ---------------- encoder: Linear + batch BN + ReLU, one block per feature ----------------
template <int IN4, int INREAL, int SIN, int SOUT>
__global__ __launch_bounds__(256)
void enc_bn_relu_kernel(const float* __restrict__ in,
                        const float* __restrict__ w, const float* __restrict__ b,
                        const float* __restrict__ gamma, const float* __restrict__ beta,
                        float* __restrict__ out) {
    const int f = blockIdx.x;
    __shared__ __align__(16) float wf[IN4 * 4];
    __shared__ float red[18];
    const int t = threadIdx.x;
    if (t < IN4 * 4) wf[t] = (t < INREAL) ? w[f * INREAL + t] : 0.f;
    __syncthreads();

    const float bf = b[f];
    float z[4];
    float s = 0.f, s2 = 0.f;
#pragma unroll
    for (int r = 0; r < 4; r++) {
        int row = t + 256 * r;
        const float4* xr = (const float4*)(in + (size_t)row * SIN);
        const float4* wv = (const float4*)wf;
        float acc = 0.f;
#pragma unroll 8
        for (int i = 0; i < IN4; i++) {
            float4 xv = xr[i];
            float4 ww = wv[i];
            acc = fmaf(xv.x, ww.x, acc);
            acc = fmaf(xv.y, ww.y, acc);
            acc = fmaf(xv.z, ww.z, acc);
            acc = fmaf(xv.w, ww.w, acc);
        }
        acc += bf;
        z[r] = acc;
        s += acc;
        s2 = fmaf(acc, acc, s2);
    }
#pragma unroll
    for (int o = 16; o > 0; o >>= 1) {
        s  += __shfl_xor_sync(0xFFFFFFFFu, s,  o);
        s2 += __shfl_xor_sync(0xFFFFFFFFu, s2, o);
    }
    int warp = t >> 5, lane = t & 31;
    if (lane == 0) { red[warp] = s; red[8 + warp] = s2; }
    __syncthreads();
    if (t == 0) {
        float S = 0.f, S2 = 0.f;
        for (int i = 0; i < 8; i++) { S += red[i]; S2 += red[8 + i]; }
        float mean = S * (1.0f / BATCH);
        float var  = S2 * (1.0f / BATCH) - mean * mean;
        float sc = gamma[f] * rsqrtf(var + 1e-5f);
        red[16] = sc;
        red[17] = beta[f] - mean * sc;
    }
    __syncthreads();
    float sc = red[16], sh = red[17];
#pragma unroll
    for (int r = 0; r < 4; r++) {
        int row = t + 256 * r;
        out[(size_t)row * SOUT + f] = fmaxf(fmaf(z[r], sc, sh), 0.f);
    }
}

// ---------------- gating MLP: 8 rows/block, 128 blocks, float4 weight staging ----------------
__global__ __launch_bounds__(256)
void gating_kernel(const float* __restrict__ lat,
                   const float* __restrict__ gw1, const float* __restrict__ gb1,
                   const float* __restrict__ gw2, const float* __restrict__ gb2,
                   const float* __restrict__ gw3, const float* __restrict__ gb3) {
    __shared__ float s_gw1[L2W * 65];
    __shared__ float s_gw2[GHW * 65];
    __shared__ float s_gw3[GHW * NE];
    __shared__ float s_gb1[GHW], s_gb2[GHW], s_gb3[NE];
    __shared__ float s_lat[8][L2W];
    __shared__ float s_a1[8][GHW];
    __shared__ float s_a2[8][GHW];
    __shared__ float s_lg[8][NE];

    const int tid = threadIdx.x;
    const int b0 = blockIdx.x * 8;

#pragma unroll
    for (int j = 0; j < 2; j++) {
        int f = tid + 256 * j;
        int o = f >> 3, kq = (f & 7) * 4;
        float4 v = ((const float4*)gw1)[f];
        s_gw1[(kq + 0) * 65 + o] = v.x;
        s_gw1[(kq + 1) * 65 + o] = v.y;
        s_gw1[(kq + 2) * 65 + o] = v.z;
        s_gw1[(kq + 3) * 65 + o] = v.w;
    }
#pragma unroll
    for (int j = 0; j < 4; j++) {
        int f = tid + 256 * j;
        int o = f >> 4, kq = (f & 15) * 4;
        float4 v = ((const float4*)gw2)[f];
        s_gw2[(kq + 0) * 65 + o] = v.x;
        s_gw2[(kq + 1) * 65 + o] = v.y;
        s_gw2[(kq + 2) * 65 + o] = v.z;
        s_gw2[(kq + 3) * 65 + o] = v.w;
    }
    if (tid < 128) {
        int e = tid >> 4, kq = (tid & 15) * 4;
        float4 v = ((const float4*)gw3)[tid];
        s_gw3[(kq + 0) * NE + e] = v.x;
        s_gw3[(kq + 1) * NE + e] = v.y;
        s_gw3[(kq + 2) * NE + e] = v.z;
        s_gw3[(kq + 3) * NE + e] = v.w;
    }
    if (tid < GHW) { s_gb1[tid] = gb1[tid]; s_gb2[tid] = gb2[tid]; }
    if (tid >= 64 && tid < 64 + NE) s_gb3[tid - 64] = gb3[tid - 64];
    if (tid >= 128 && tid < 192) {
        int u = tid - 128;
        int r = u >> 3, kq = (u & 7) * 4;
        float4 v = *(const float4*)(lat + (size_t)(b0 + r) * L2W + kq);
        s_lat[r][kq + 0] = v.x; s_lat[r][kq + 1] = v.y;
        s_lat[r][kq + 2] = v.z; s_lat[r][kq + 3] = v.w;
    }
    __syncthreads();

    const int ox = tid & 63;
    const int rg = tid >> 6;
    const int r0 = rg * 2, r1 = rg * 2 + 1;

    {
        float a0 = s_gb1[ox], a1 = s_gb1[ox];
#pragma unroll
        for (int k = 0; k < L2W; k++) {
            float w = s_gw1[k * 65 + ox];
            a0 = fmaf(s_lat[r0][k], w, a0);
            a1 = fmaf(s_lat[r1][k], w, a1);
        }
        s_a1[r0][ox] = (a0 > 0.f) ? a0 : expm1f(a0);
        s_a1[r1][ox] = (a1 > 0.f) ? a1 : expm1f(a1);
    }
    __syncthreads();

    {
        float a0 = s_gb2[ox], a1 = s_gb2[ox];
#pragma unroll
        for (int k = 0; k < GHW; k++) {
            float w = s_gw2[k * 65 + ox];
            a0 = fmaf(s_a1[r0][k], w, a0);
            a1 = fmaf(s_a1[r1][k], w, a1);
        }
        s_a2[r0][ox] = (a0 > 0.f) ? a0 : expm1f(a0);
        s_a2[r1][ox] = (a1 > 0.f) ? a1 : expm1f(a1);
    }
    __syncthreads();

    if (tid < 64) {
        int e = tid & 7, r = tid >> 3;
        float acc = s_gb3[e];
#pragma unroll
        for (int k = 0; k < GHW; k++) acc = fmaf(s_a2[r][k], s_gw3[k * NE + e], acc);
        s_lg[r][e] = acc;
    }
    __syncthreads();

    if (tid < 8) {
        float m = s_lg[tid][0];
#pragma unroll
        for (int e = 1; e < NE; e++) m = fmaxf(m, s_lg[tid][e]);
        float ex[NE];
        float ssum = 0.f;
#pragma unroll
        for (int e = 0; e < NE; e++) { ex[e] = expf(s_lg[tid][e] - m); ssum += ex[e]; }
        float inv = 1.0f / ssum;
#pragma unroll
        for (int e = 0; e < NE; e++) g_bc[(size_t)(b0 + tid) * NE + e] = ex[e] * inv;
    }
}

// ---------------- gen GEMM with packed f32x2 FMAs ----------------
// BM=128, BN=128, BK=16, 256 threads, 8x8 microtile (pairs along N).
// A smem tile stored DUPLICATED: As2[k][2m]=As2[k][2m+1]=A[m][k], so LDS.128
// yields two (a,a) broadcast pairs directly. W pairs via conflict-free LDS.64.
template <int KSIZE, int ASTRIDE, int OUTN, int INREAL>
__global__ __launch_bounds__(256)
void gen_f32x2_kernel(const float* __restrict__ A,
                      const float* __restrict__ W,
                      const float* __restrict__ bias,
                      float* __restrict__ part) {
    constexpr int BM = 128, BN = 128, BK = 16;
    constexpr int KT = KSIZE / BK;
    constexpr int ASTR = 2 * BM + 4;      // duplicated row + 4-float stagger
    __shared__ __align__(16) float As2[2][BK][ASTR];
    __shared__ __align__(16) float Ws[2][BK][BN];
    __shared__ __align__(16) float sbias[BN];

    const int e  = blockIdx.z;
    const int m0 = blockIdx.y * BM;
    const int n0 = blockIdx.x * BN;
    const int tid = threadIdx.x;
    const int tx = tid & 15;               // n group: cols 2tx + 32j
    const int ty = tid >> 4;               // m group: rows 8ty..8ty+7

    // A gmem map: row a_m, 8 consecutive k at a_k
    const int a_m = tid >> 1;
    const int a_k = (tid & 1) * 8;
    // W gmem map: row w_k, 8 consecutive n at w_n
    const int w_k = tid >> 4;
    const int w_n = (tid & 15) * 8;

    const float* Wbase = W + (size_t)e * INREAL * OUTN;
    if (tid < BN) sbias[tid] = bias[(size_t)e * OUTN + n0 + tid];

    u64 acc[8][4];
#pragma unroll
    for (int i = 0; i < 8; i++)
#pragma unroll
        for (int j = 0; j < 4; j++) acc[i][j] = 0ull;

    float4 pa0, pa1, pw0, pw1;

    // prologue: load tile 0
    {
        const float* ap = A + (size_t)(m0 + a_m) * ASTRIDE + a_k;
        pa0 = *(const float4*)(ap);
        pa1 = *(const float4*)(ap + 4);
        int gk = w_k;
        if (KSIZE != INREAL) gk = (gk < INREAL) ? gk : (INREAL - 1);
        const float* wp = Wbase + (size_t)gk * OUTN + n0 + w_n;
        pw0 = *(const float4*)(wp);
        pw1 = *(const float4*)(wp + 4);
    }
    // store tile 0 -> buf 0 (A duplicated)
    {
        float* as = &As2[0][a_k][2 * a_m];
        ((float2*)(&As2[0][a_k + 0][2 * a_m]))[0] = make_float2(pa0.x, pa0.x);
        ((float2*)(&As2[0][a_k + 1][2 * a_m]))[0] = make_float2(pa0.y, pa0.y);
        ((float2*)(&As2[0][a_k + 2][2 * a_m]))[0] = make_float2(pa0.z, pa0.z);
        ((float2*)(&As2[0][a_k + 3][2 * a_m]))[0] = make_float2(pa0.w, pa0.w);
        ((float2*)(&As2[0][a_k + 4][2 * a_m]))[0] = make_float2(pa1.x, pa1.x);
        ((float2*)(&As2[0][a_k + 5][2 * a_m]))[0] = make_float2(pa1.y, pa1.y);
        ((float2*)(&As2[0][a_k + 6][2 * a_m]))[0] = make_float2(pa1.z, pa1.z);
        ((float2*)(&As2[0][a_k + 7][2 * a_m]))[0] = make_float2(pa1.w, pa1.w);
        (void)as;
        *(float4*)&Ws[0][w_k][w_n]     = pw0;
        *(float4*)&Ws[0][w_k][w_n + 4] = pw1;
    }
    __syncthreads();

    for (int kt = 0; kt < KT; kt++) {
        const int buf = kt & 1;
        // prefetch next tile
        if (kt + 1 < KT) {
            const int k0 = (kt + 1) * BK;
            const float* ap = A + (size_t)(m0 + a_m) * ASTRIDE + k0 + a_k;
            pa0 = *(const float4*)(ap);
            pa1 = *(const float4*)(ap + 4);
            int gk = k0 + w_k;
            if (KSIZE != INREAL) gk = (gk < INREAL) ? gk : (INREAL - 1);
            const float* wp = Wbase + (size_t)gk * OUTN + n0 + w_n;
            pw0 = *(const float4*)(wp);
            pw1 = *(const float4*)(wp + 4);
        }
        // compute current tile
#pragma unroll
        for (int k = 0; k < BK; k++) {
            const float* ar = &As2[buf][k][16 * ty];
            ulonglong2 av0 = *(const ulonglong2*)(ar + 0);
            ulonglong2 av1 = *(const ulonglong2*)(ar + 4);
            ulonglong2 av2 = *(const ulonglong2*)(ar + 8);
            ulonglong2 av3 = *(const ulonglong2*)(ar + 12);
            u64 wp_[4];
#pragma unroll
            for (int j = 0; j < 4; j++)
                wp_[j] = *(const u64*)&Ws[buf][k][2 * tx + 32 * j];
            u64 ap_[8] = {av0.x, av0.y, av1.x, av1.y, av2.x, av2.y, av3.x, av3.y};
#pragma unroll
            for (int i = 0; i < 8; i++)
#pragma unroll
                for (int j = 0; j < 4; j++)
                    acc[i][j] = ffma2(ap_[i], wp_[j], acc[i][j]);
        }
        // store prefetched tile -> other buffer
        if (kt + 1 < KT) {
            const int nb = buf ^ 1;
            ((float2*)(&As2[nb][a_k + 0][2 * a_m]))[0] = make_float2(pa0.x, pa0.x);
            ((float2*)(&As2[nb][a_k + 1][2 * a_m]))[0] = make_float2(pa0.y, pa0.y);
            ((float2*)(&As2[nb][a_k + 2][2 * a_m]))[0] = make_float2(pa0.z, pa0.z);
            ((float2*)(&As2[nb][a_k + 3][2 * a_m]))[0] = make_float2(pa0.w, pa0.w);
            ((float2*)(&As2[nb][a_k + 4][2 * a_m]))[0] = make_float2(pa1.x, pa1.x);
            ((float2*)(&As2[nb][a_k + 5][2 * a_m]))[0] = make_float2(pa1.y, pa1.y);
            ((float2*)(&As2[nb][a_k + 6][2 * a_m]))[0] = make_float2(pa1.z, pa1.z);
            ((float2*)(&As2[nb][a_k + 7][2 * a_m]))[0] = make_float2(pa1.w, pa1.w);
            *(float4*)&Ws[nb][w_k][w_n]     = pw0;
            *(float4*)&Ws[nb][w_k][w_n + 4] = pw1;
            __syncthreads();
        }
    }

    // epilogue: add bias, write float2 pairs
#pragma unroll
    for (int i = 0; i < 8; i++) {
        const int row = m0 + ty * 8 + i;
        float* pb = part + ((size_t)e * BATCH + row) * OUTN + n0;
#pragma unroll
        for (int j = 0; j < 4; j++) {
            const int n = 2 * tx + 32 * j;
            u64 sb = *(const u64*)&sbias[n];
            u64 o = fadd2(acc[i][j], sb);
            *(u64*)(pb + n) = o;
        }
    }
}

// ---------------- gen layer 3: scalar double-buffered (BM=64, TM=4, BN=64) ----------------
template <int KSIZE, int ASTRIDE, int OUTN, int INREAL, int BM, int TM>
__global__ __launch_bounds__(256)
void gen_expert_kernel(const float* __restrict__ A,
                       const float* __restrict__ W,
                       const float* __restrict__ bias,
                       float* __restrict__ part) {
    constexpr int BN = 64, BK = 32;
    constexpr int KT = KSIZE / BK;
    constexpr int F4A = BM * BK / 1024;
    __shared__ __align__(16) float As[2][BK][BM + 4];
    __shared__ __align__(16) float Ws[2][BK][BN];
    __shared__ float sbias[BN];

    const int e  = blockIdx.z;
    const int m0 = blockIdx.y * BM;
    const int n0 = blockIdx.x * BN;
    const int tid = threadIdx.x;
    const int tx = tid & 15;
    const int ty = tid >> 4;

    int a_r[F4A], a_kq[F4A];
#pragma unroll
    for (int j = 0; j < F4A; j++) {
        int idx = tid * F4A + j;
        a_r[j] = idx >> 3;
        a_kq[j] = (idx & 7) * 4;
    }
    const int wk = tid >> 3;
    const int wc = (tid & 7) * 8;

    const float* Wbase = W + (size_t)e * INREAL * OUTN;
    if (tid < BN) sbias[tid] = bias[(size_t)e * OUTN + n0 + tid];

    float acc[TM][4];
#pragma unroll
    for (int i = 0; i < TM; i++)
#pragma unroll
        for (int j = 0; j < 4; j++) acc[i][j] = 0.f;

    float4 pa[F4A];
    float4 pw0, pw1;

    {
#pragma unroll
        for (int j = 0; j < F4A; j++)
            pa[j] = *(const float4*)(A + (size_t)(m0 + a_r[j]) * ASTRIDE + a_kq[j]);
        int gk = wk;
        if (KSIZE != INREAL) gk = (gk < INREAL) ? gk : (INREAL - 1);
        const float* wp = Wbase + (size_t)gk * OUTN + n0;
        pw0 = *(const float4*)(wp + wc);
        pw1 = *(const float4*)(wp + wc + 4);
    }
    {
#pragma unroll
        for (int j = 0; j < F4A; j++) {
            As[0][a_kq[j] + 0][a_r[j]] = pa[j].x;
            As[0][a_kq[j] + 1][a_r[j]] = pa[j].y;
            As[0][a_kq[j] + 2][a_r[j]] = pa[j].z;
            As[0][a_kq[j] + 3][a_r[j]] = pa[j].w;
        }
        *(float4*)&Ws[0][wk][wc]     = pw0;
        *(float4*)&Ws[0][wk][wc + 4] = pw1;
    }
    __syncthreads();

    for (int kt = 0; kt < KT; kt++) {
        const int buf = kt & 1;
        if (kt + 1 < KT) {
            const int k0 = (kt + 1) * BK;
#pragma unroll
            for (int j = 0; j < F4A; j++)
                pa[j] = *(const float4*)(A + (size_t)(m0 + a_r[j]) * ASTRIDE + k0 + a_kq[j]);
            int gk = k0 + wk;
            if (KSIZE != INREAL) gk = (gk < INREAL) ? gk : (INREAL - 1);
            const float* wp = Wbase + (size_t)gk * OUTN + n0;
            pw0 = *(const float4*)(wp + wc);
            pw1 = *(const float4*)(wp + wc + 4);
        }
#pragma unroll 8
        for (int k = 0; k < BK; k++) {
            float4 w = *(const float4*)&Ws[buf][k][tx * 4];
#pragma unroll
            for (int i4 = 0; i4 < TM / 4; i4++) {
                float4 a = *(const float4*)&As[buf][k][ty * TM + i4 * 4];
                acc[i4 * 4 + 0][0] = fmaf(a.x, w.x, acc[i4 * 4 + 0][0]);
                acc[i4 * 4 + 0][1] = fmaf(a.x, w.y, acc[i4 * 4 + 0][1]);
                acc[i4 * 4 + 0][2] = fmaf(a.x, w.z, acc[i4 * 4 + 0][2]);
                acc[i4 * 4 + 0][3] = fmaf(a.x, w.w, acc[i4 * 4 + 0][3]);
                acc[i4 * 4 + 1][0] = fmaf(a.y, w.x, acc[i4 * 4 + 1][0]);
                acc[i4 * 4 + 1][1] = fmaf(a.y, w.y, acc[i4 * 4 + 1][1]);
                acc[i4 * 4 + 1][2] = fmaf(a.y, w.z, acc[i4 * 4 + 1][2]);
                acc[i4 * 4 + 1][3] = fmaf(a.y, w.w, acc[i4 * 4 + 1][3]);
                acc[i4 * 4 + 2][0] = fmaf(a.z, w.x, acc[i4 * 4 + 2][0]);
                acc[i4 * 4 + 2][1] = fmaf(a.z, w.y, acc[i4 * 4 + 2][1]);
                acc[i4 * 4 + 2][2] = fmaf(a.z, w.z, acc[i4 * 4 + 2][2]);
                acc[i4 * 4 + 2][3] = fmaf(a.z, w.w, acc[i4 * 4 + 2][3]);
                acc[i4 * 4 + 3][0] = fmaf(a.w, w.x, acc[i4 * 4 + 3][0]);
                acc[i4 * 4 + 3][1] = fmaf(a.w, w.y, acc[i4 * 4 + 3][1]);
                acc[i4 * 4 + 3][2] = fmaf(a.w, w.z, acc[i4 * 4 + 3][2]);
                acc[i4 * 4 + 3][3] = fmaf(a.w, w.w, acc[i4 * 4 + 3][3]);
            }
        }
        if (kt + 1 < KT) {
            const int nb = buf ^ 1;
#pragma unroll
            for (int j = 0; j < F4A; j++) {
                As[nb][a_kq[j] + 0][a_r[j]] = pa[j].x;
                As[nb][a_kq[j] + 1][a_r[j]] = pa[j].y;
                As[nb][a_kq[j] + 2][a_r[j]] = pa[j].z;
                As[nb][a_kq[j] + 3][a_r[j]] = pa[j].w;
            }
            *(float4*)&Ws[nb][wk][wc]     = pw0;
            *(float4*)&Ws[nb][wk][wc + 4] = pw1;
            __syncthreads();
        }
    }

#pragma unroll
    for (int i = 0; i < TM; i++) {
        const int row = m0 + ty * TM + i;
        float* pp = part + ((size_t)e * BATCH + row) * OUTN + n0 + tx * 4;
        float4 o;
        o.x = acc[i][0] + sbias[tx * 4 + 0];
        o.y = acc[i][1] + sbias[tx * 4 + 1];
        o.z = acc[i][2] + sbias[tx * 4 + 2];
        o.w = acc[i][3] + sbias[tx * 4 + 3];
        *(float4*)pp = o;
    }
}

// ---------------- combine experts with bc weights (+ optional ELU), vectorized ----------------
template <bool ACT>
__global__ void combine_vec_kernel(const float* __restrict__ part, float* __restrict__ out) {
    const int i = blockIdx.x * 256 + threadIdx.x;
    if (i >= BATCH * (HID / 4)) return;
    const int b = i >> 6;
    const float* bcp = g_bc + (size_t)b * NE;
    float4 s = make_float4(0.f, 0.f, 0.f, 0.f);
#pragma unroll
    for (int e = 0; e < NE; e++) {
        float c = bcp[e];
        float4 p = ((const float4*)part)[(size_t)e * BATCH * (HID / 4) + i];
        s.x = fmaf(c, p.x, s.x);
        s.y = fmaf(c, p.y, s.y);
        s.z = fmaf(c, p.z, s.z);
        s.w = fmaf(c, p.w, s.w);
    }
    if (ACT) {
        s.x = (s.x > 0.f) ? s.x : expm1f(s.x);
        s.y = (s.y > 0.f) ? s.y : expm1f(s.y);
        s.z = (s.z > 0.f) ? s.z : expm1f(s.z);
        s.w = (s.w > 0.f) ? s.w : expm1f(s.w);
    }
    ((float4*)out)[i] = s;
}

// final combine: padded stride 64 -> write 51
__global__ void combine_final_kernel(const float* __restrict__ part, float* __restrict__ out) {
    const int i = blockIdx.x * 256 + threadIdx.x;
    if (i >= BATCH * DOUT) return;
    const int b = i / DOUT;
    const int n = i - b * DOUT;
    const float* bcp = g_bc + (size_t)b * NE;
    float s = 0.f;
#pragma unroll
    for (int e = 0; e < NE; e++)
        s = fmaf(bcp[e], part[((size_t)e * BATCH + b) * DOPAD + n], s);
    out[i] = s;
}

// ---------------- launch ----------------
extern "C" void kernel_launch(void* const* d_in, const int* in_sizes, int n_in,
                              void* d_out, int out_size) {
    const float* x      = (const float*)d_in[0];
    const float* w1     = (const float*)d_in[1];
    const float* b1     = (const float*)d_in[2];
    const float* gamma1 = (const float*)d_in[3];
    const float* beta1  = (const float*)d_in[4];
    const float* w2     = (const float*)d_in[5];
    const float* b2     = (const float*)d_in[6];
    const float* gamma2 = (const float*)d_in[7];
    const float* beta2  = (const float*)d_in[8];
    const float* gw1    = (const float*)d_in[9];
    const float* gb1    = (const float*)d_in[10];
    const float* gw2    = (const float*)d_in[11];
    const float* gb2    = (const float*)d_in[12];
    const float* gw3    = (const float*)d_in[13];
    const float* gb3    = (const float*)d_in[14];
    const float* ew1    = (const float*)d_in[15];
    const float* eb1    = (const float*)d_in[16];
    const float* ew2    = (const float*)d_in[17];
    const float* eb2    = (const float*)d_in[18];
    const float* ew3    = (const float*)d_in[19];
    const float* eb3    = (const float*)d_in[20];

    float *p_xs, *p_enc1, *p_lat, *p_h1, *p_h2, *p_part, *p_w3p, *p_b3p;
    cudaGetSymbolAddress((void**)&p_xs,   g_xs);
    cudaGetSymbolAddress((void**)&p_enc1, g_enc1);
    cudaGetSymbolAddress((void**)&p_lat,  g_lat);
    cudaGetSymbolAddress((void**)&p_h1,   g_h1);
    cudaGetSymbolAddress((void**)&p_h2,   g_h2);
    cudaGetSymbolAddress((void**)&p_part, g_part);
    cudaGetSymbolAddress((void**)&p_w3p,  g_w3p);
    cudaGetSymbolAddress((void**)&p_b3p,  g_b3p);

    const int prepN = BATCH * XPAD + NE * HID * DOPAD + NE * DOPAD;
    prep_kernel<<<(prepN + 255) / 256, 256>>>(x, ew3, eb3);

    enc_bn_relu_kernel<32, DIN, XPAD, L1W><<<L1W, 256>>>(p_xs, w1, b1, gamma1, beta1, p_enc1);
    enc_bn_relu_kernel<16, L1W, L1W, L2W><<<L2W, 256>>>(p_enc1, w2, b2, gamma2, beta2, p_lat);

    gating_kernel<<<BATCH / 8, 256>>>(p_lat, gw1, gb1, gw2, gb2, gw3, gb3);

    // layer 1: xs[1024,128(pad)] x ew1[8,103,256]  f32x2, BM=128,BN=128
    gen_f32x2_kernel<XPAD, XPAD, HID, DIN>
        <<<dim3(HID / 128, BATCH / 128, NE), 256>>>(p_xs, ew1, eb1, p_part);
    combine_vec_kernel<true><<<(BATCH * HID / 4 + 255) / 256, 256>>>(p_part, p_h1);

    // layer 2: h1[1024,256] x ew2[8,256,256]  f32x2, BM=128,BN=128
    gen_f32x2_kernel<HID, HID, HID, HID>
        <<<dim3(HID / 128, BATCH / 128, NE), 256>>>(p_h1, ew2, eb2, p_part);
    combine_vec_kernel<true><<<(BATCH * HID / 4 + 255) / 256, 256>>>(p_part, p_h2);

    // layer 3: h2[1024,256] x w3p[8,256,64(pad)]  scalar BM=64, TM=4 -> 128 blocks
    gen_expert_kernel<HID, HID, DOPAD, HID, 64, 4>
        <<<dim3(1, BATCH / 64, NE), 256>>>(p_h2, p_w3p, p_b3p, p_part);
    combine_final_kernel<<<(BATCH * DOUT + 255) / 256, 256>>>(p_part, (float*)d_out);
}